// round 14
// baseline (speedup 1.0000x reference)
#include <cuda_runtime.h>
#include <cuda_bf16.h>
#include <cuda_fp16.h>
#include <math.h>
#include <stdint.h>

#define SEQ   2048
#define NH    16
#define DH    64
#define DM    1024
#define DM3   3072
#define BATCH 2
#define MROWS (BATCH*SEQ)   // 4096
#define GRID_SK 148
#define GRID2  (2*GRID_SK)  // 296

// ---------------- scratch (device globals; no allocations allowed) ----------
__device__ float g_bias[NH*4096];            // per-head bias vs (j-i)+2048
__device__ unsigned short g_hh[MROWS*DM];    // hidden bf16 hi
__device__ unsigned short g_hl[MROWS*DM];    // hidden bf16 lo
__device__ unsigned short g_hf[MROWS*DM];    // hidden fp16 single (V path)
__device__ unsigned short g_xh[MROWS*DM3];   // Q,K bf16-hi | V fp16   [row][3072]
__device__ unsigned short g_xl[MROWS*DM3];   // Q,K bf16-lo | (unused)
__device__ unsigned short g_ah[MROWS*DM];    // attn out fp16 single
__device__ unsigned short g_wh[4][DM*DM];    // W^T [n][k]: q,k bf16-hi; v,o fp16
__device__ unsigned short g_wl[4][DM*DM];    // q,k bf16-lo; v,o unused
__device__ float g_scr[GRID2][256*64];       // f16-GEMM partials (256 thr x FACC=64)
__device__ float g_scrq[GRID_SK][256*128];   // QK partials (256 thr x ACCN=128)
__device__ int   g_flag[GRID2+2];            // f16-GEMM flags (self-resetting)
__device__ int   g_flagq[GRID_SK+1];         // QK flags

// ======================= helpers =============================================
__device__ __forceinline__ uint32_t smem_u32(const void* p) {
    uint32_t a;
    asm("{ .reg .u64 t; cvta.to.shared.u64 t, %1; cvt.u32.u64 %0, t; }" : "=r"(a) : "l"(p));
    return a;
}
__device__ __forceinline__ void cp_async16(uint32_t dst, const void* src) {
    asm volatile("cp.async.cg.shared.global [%0], [%1], 16;" :: "r"(dst), "l"(src));
}
#define CP_COMMIT() asm volatile("cp.async.commit_group;" ::: "memory")
#define CP_WAIT(N)  asm volatile("cp.async.wait_group %0;" :: "n"(N) : "memory")

#define LDSM4(r, addr) \
    asm volatile("ldmatrix.sync.aligned.m8n8.x4.shared.b16 {%0,%1,%2,%3}, [%4];" \
        : "=r"((r)[0]), "=r"((r)[1]), "=r"((r)[2]), "=r"((r)[3]) : "r"(addr))
#define LDSM4T(r, addr) \
    asm volatile("ldmatrix.sync.aligned.m8n8.x4.trans.shared.b16 {%0,%1,%2,%3}, [%4];" \
        : "=r"((r)[0]), "=r"((r)[1]), "=r"((r)[2]), "=r"((r)[3]) : "r"(addr))

#define MMA16816(c, a, b0, b1) \
    asm volatile("mma.sync.aligned.m16n8k16.row.col.f32.bf16.bf16.f32 " \
        "{%0,%1,%2,%3}, {%4,%5,%6,%7}, {%8,%9}, {%0,%1,%2,%3};" \
        : "+f"((c)[0]), "+f"((c)[1]), "+f"((c)[2]), "+f"((c)[3]) \
        : "r"((a)[0]), "r"((a)[1]), "r"((a)[2]), "r"((a)[3]), "r"(b0), "r"(b1))

#define MMAF16(c, a, b0, b1) \
    asm volatile("mma.sync.aligned.m16n8k16.row.col.f32.f16.f16.f32 " \
        "{%0,%1,%2,%3}, {%4,%5,%6,%7}, {%8,%9}, {%0,%1,%2,%3};" \
        : "+f"((c)[0]), "+f"((c)[1]), "+f"((c)[2]), "+f"((c)[3]) \
        : "r"((a)[0]), "r"((a)[1]), "r"((a)[2]), "r"((a)[3]), "r"(b0), "r"(b1))

__device__ __forceinline__ uint32_t pack_bf2(float x, float y) {
    __nv_bfloat162 t = __floats2bfloat162_rn(x, y);
    return *(uint32_t*)&t;
}
__device__ __forceinline__ float2 unpack_bf2(uint32_t u) {
    __nv_bfloat162 t = *(__nv_bfloat162*)&u;
    return __bfloat1622float2(t);
}
__device__ __forceinline__ uint32_t pack_h2(float x, float y) {
    __half2 t = __floats2half2_rn(x, y);
    return *(uint32_t*)&t;
}

// fast exp on the FMA pipe (args <= 0; clamp keeps scale exponent valid)
__device__ __forceinline__ float expp(float x) {
    x = fmaxf(x, -80.0f);
    float y = x * 1.4426950408889634f;
    float t = y + 12582912.0f;
    int   n = __float_as_int(t) - 0x4B400000;
    float f = y - (t - 12582912.0f);
    float g = f * 0.6931471805599453f;
    float p = fmaf(g, 0.008333333f, 0.041666668f);
    p = fmaf(p, g, 0.16666667f);
    p = fmaf(p, g, 0.5f);
    p = fmaf(p, g, 1.0f);
    p = fmaf(p, g, 1.0f);
    return p * __int_as_float((n + 127) << 23);
}

// ------ fp32 -> bf16 hi/lo split + fp16 single (elementwise) ----------------
__global__ void convert_split(const float* __restrict__ x,
                              unsigned short* __restrict__ oh,
                              unsigned short* __restrict__ ol,
                              unsigned short* __restrict__ of) {
    int i = blockIdx.x * blockDim.x + threadIdx.x;
    float4 v = ((const float4*)x)[i];
    uint32_t h01 = pack_bf2(v.x, v.y);
    uint32_t h23 = pack_bf2(v.z, v.w);
    float2 f01 = unpack_bf2(h01);
    float2 f23 = unpack_bf2(h23);
    uint32_t* ph = (uint32_t*)(oh + 4*(size_t)i);
    uint32_t* pl = (uint32_t*)(ol + 4*(size_t)i);
    uint32_t* pf = (uint32_t*)(of + 4*(size_t)i);
    ph[0] = h01; ph[1] = h23;
    pl[0] = pack_bf2(v.x - f01.x, v.y - f01.y);
    pl[1] = pack_bf2(v.z - f23.x, v.w - f23.y);
    pf[0] = pack_h2(v.x, v.y);
    pf[1] = pack_h2(v.z, v.w);
}

// ---- W converts (z=0..3) + bias table (z=4), one launch ---------------------
__global__ void convert_w_all(const float* __restrict__ W0, const float* __restrict__ W1,
                              const float* __restrict__ W2, const float* __restrict__ W3,
                              const float* __restrict__ rel_bias) {
    __shared__ float t[32][33];
    int z = blockIdx.z;
    int tx = threadIdx.x, ty = threadIdx.y;
    if (z == 4) {
        if (blockIdx.y != 0 || blockIdx.x >= NH) return;
        int h = blockIdx.x;
        int tid = ty * 32 + tx;
        for (int i = tid; i < 4096; i += 256) {
            int delta = i - 2048;
            int rb = (delta > 0) ? 16 : 0;
            int ar = delta < 0 ? -delta : delta;
            int bucket;
            if (ar < 8) {
                bucket = rb + ar;
            } else {
                int l = 8 + (int)(2.0f * log2f((float)ar * 0.125f));
                bucket = rb + (l > 15 ? 15 : l);
            }
            g_bias[h*4096 + i] = rel_bias[bucket*NH + h];
        }
        return;
    }
    const float* W = (z == 0) ? W0 : (z == 1) ? W1 : (z == 2) ? W2 : W3;
    unsigned short* oh = (unsigned short*)g_wh + (size_t)z * DM * DM;
    unsigned short* ol = (unsigned short*)g_wl + (size_t)z * DM * DM;
    int n0 = blockIdx.x * 32, k0 = blockIdx.y * 32;
    #pragma unroll
    for (int j = 0; j < 32; j += 8)
        t[ty + j][tx] = W[(size_t)(k0 + ty + j) * DM + n0 + tx];
    __syncthreads();
    #pragma unroll
    for (int j = 0; j < 32; j += 8) {
        float v = t[tx][ty + j];
        size_t o = (size_t)(n0 + ty + j) * DM + k0 + tx;
        if (z >= 2) {
            __half h = __float2half_rn(v);
            oh[o] = *(unsigned short*)&h;
        } else {
            __nv_bfloat16 h = __float2bfloat16_rn(v);
            oh[o] = *(unsigned short*)&h;
            __nv_bfloat16 l = __float2bfloat16_rn(v - __bfloat162float(h));
            ol[o] = *(unsigned short*)&l;
        }
    }
}

// ============== stream-K QK GEMM (bf16 3-pass, out bf16 hi/lo) ===============
#define PITCHB 80

__device__ __forceinline__ void tile_epi_qk(const float* acc, int m0, int n0,
                                            int wm, int wn, int lane,
                                            unsigned short* Ch, unsigned short* Cl)
{
    const int rbase = m0 + wm*64 + (lane >> 2);
    const int cbase = n0 + wn*64 + (lane & 3) * 2;
    #pragma unroll
    for (int mt = 0; mt < 4; mt++) {
        #pragma unroll
        for (int nt = 0; nt < 8; nt++) {
            const float* q = acc + (mt*8 + nt)*4;
            int row = rbase + mt*16;
            int col = cbase + nt*8;
            uint32_t h0 = pack_bf2(q[0], q[1]);
            float2 f0 = unpack_bf2(h0);
            *(uint32_t*)&Ch[(size_t)row * DM3 + col] = h0;
            *(uint32_t*)&Cl[(size_t)row * DM3 + col] = pack_bf2(q[0]-f0.x, q[1]-f0.y);
            uint32_t h1 = pack_bf2(q[2], q[3]);
            float2 f1 = unpack_bf2(h1);
            *(uint32_t*)&Ch[(size_t)(row+8) * DM3 + col] = h1;
            *(uint32_t*)&Cl[(size_t)(row+8) * DM3 + col] = pack_bf2(q[2]-f1.x, q[3]-f1.y);
        }
    }
}

#define QSAH 0
#define QSAL (128*PITCHB)
#define QSBH (2*128*PITCHB)
#define QSBL (QSBH + 256*PITCHB)
#define QSTG (QSBH + 2*256*PITCHB)

__global__ __launch_bounds__(256, 1) void gemm_qk(
    const unsigned short* __restrict__ Ah, const unsigned short* __restrict__ Al,
    const unsigned short* __restrict__ Bh, const unsigned short* __restrict__ Bl,
    unsigned short* __restrict__ Ch, unsigned short* __restrict__ Cl)
{
    extern __shared__ char smem[];
    const uint32_t sb0 = smem_u32(smem);
    const int tid  = threadIdx.x;
    const int lane = tid & 31;
    const int wm   = (tid >> 5) >> 2;
    const int wn   = (tid >> 5) & 3;
    const int cta  = blockIdx.x;
    const int G    = gridDim.x;

    const int total = 8192;           // 256 tiles (32m x 8n) x 32 chunks
    const int s = (int)(((long long)cta       * total) / G);
    const int e = (int)(((long long)(cta + 1) * total) / G);

    const uint32_t loff = (lane & 15) * PITCHB + ((lane >> 4) & 1) * 16;

    float acc[128];
    #pragma unroll
    for (int i = 0; i < 128; i++) acc[i] = 0.0f;

    #define LOAD_CHUNK(c, stg) do { \
        int t_  = (c) >> 5; \
        int m0_ = (t_ >> 3) * 128, n0_ = (t_ & 7) * 256, k0_ = ((c) & 31) * 32; \
        const uint32_t sb_ = sb0 + (stg) * QSTG; \
        _Pragma("unroll") \
        for (int tt = 0; tt < 2; tt++) { \
            int idx = tid + tt*256; int r = idx >> 2, cc = idx & 3; \
            cp_async16(sb_ + QSAH + r*PITCHB + cc*16, Ah + (size_t)(m0_+r)*DM + k0_ + cc*8); \
            cp_async16(sb_ + QSAL + r*PITCHB + cc*16, Al + (size_t)(m0_+r)*DM + k0_ + cc*8); \
        } \
        _Pragma("unroll") \
        for (int tt = 0; tt < 4; tt++) { \
            int idx = tid + tt*256; int r = idx >> 2, cc = idx & 3; \
            cp_async16(sb_ + QSBH + r*PITCHB + cc*16, Bh + (size_t)(n0_+r)*DM + k0_ + cc*8); \
            cp_async16(sb_ + QSBL + r*PITCHB + cc*16, Bl + (size_t)(n0_+r)*DM + k0_ + cc*8); \
        } \
        CP_COMMIT(); \
    } while (0)

    LOAD_CHUNK(s, 0);
    if (s + 1 < e) LOAD_CHUNK(s + 1, 1);
    int cur = 0;

    #pragma unroll 1
    for (int c = s; c < e; c++) {
        if (c + 1 < e) { CP_WAIT(1); } else { CP_WAIT(0); }
        __syncthreads();
        if (c + 2 < e) {
            int pf = cur - 1; if (pf < 0) pf = 2;
            LOAD_CHUNK(c + 2, pf);
        }

        const uint32_t sb = sb0 + cur * QSTG;
        cur = (cur == 2) ? 0 : cur + 1;

        #pragma unroll
        for (int kk = 0; kk < 2; kk++) {
            const uint32_t koff = kk * 32;
            uint32_t a[16], a2[16], bhf[16], blf[16];
            #pragma unroll
            for (int mt = 0; mt < 4; mt++)
                LDSM4(a + 4*mt,  sb + QSAH + (wm*64 + mt*16)*PITCHB + loff + koff);
            #pragma unroll
            for (int p = 0; p < 4; p++)
                LDSM4(bhf + 4*p, sb + QSBH + (wn*64 + p*16)*PITCHB + loff + koff);
            #pragma unroll
            for (int mt = 0; mt < 4; mt++)
                LDSM4(a2 + 4*mt, sb + QSAL + (wm*64 + mt*16)*PITCHB + loff + koff);
            #pragma unroll
            for (int p = 0; p < 4; p++)
                LDSM4(blf + 4*p, sb + QSBL + (wn*64 + p*16)*PITCHB + loff + koff);
            #pragma unroll
            for (int mt = 0; mt < 4; mt++)
                #pragma unroll
                for (int p = 0; p < 4; p++) {
                    MMA16816(acc + (mt*8 + 2*p)*4,   a + 4*mt, bhf[4*p+0], bhf[4*p+2]);
                    MMA16816(acc + (mt*8 + 2*p+1)*4, a + 4*mt, bhf[4*p+1], bhf[4*p+3]);
                }
            #pragma unroll
            for (int mt = 0; mt < 4; mt++)
                #pragma unroll
                for (int p = 0; p < 4; p++) {
                    MMA16816(acc + (mt*8 + 2*p)*4,   a2 + 4*mt, bhf[4*p+0], bhf[4*p+2]);
                    MMA16816(acc + (mt*8 + 2*p+1)*4, a2 + 4*mt, bhf[4*p+1], bhf[4*p+3]);
                }
            #pragma unroll
            for (int mt = 0; mt < 4; mt++)
                #pragma unroll
                for (int p = 0; p < 4; p++) {
                    MMA16816(acc + (mt*8 + 2*p)*4,   a + 4*mt, blf[4*p+0], blf[4*p+2]);
                    MMA16816(acc + (mt*8 + 2*p+1)*4, a + 4*mt, blf[4*p+1], blf[4*p+3]);
                }
        }

        const int t = c >> 5;
        if ((c & 31) == 31) {
            if (t * 32 >= s) {
                tile_epi_qk(acc, (t >> 3) * 128, (t & 7) * 256, wm, wn, lane, Ch, Cl);
            } else {
                float* slot = g_scrq[cta] + (size_t)tid * 128;
                #pragma unroll
                for (int i = 0; i < 128; i += 4)
                    *(float4*)&slot[i] = *(float4*)&acc[i];
                __threadfence();
                __syncthreads();
                if (tid == 0) atomicExch(&g_flagq[cta], 1);
            }
            #pragma unroll
            for (int i = 0; i < 128; i++) acc[i] = 0.0f;
        } else if (c == e - 1) {
            if (tid == 0) {
                while (atomicAdd(&g_flagq[cta + 1], 0) == 0) { __nanosleep(64); }
                atomicExch(&g_flagq[cta + 1], 0);
                __threadfence();
            }
            __syncthreads();
            const float* slot = g_scrq[cta + 1] + (size_t)tid * 128;
            #pragma unroll
            for (int i = 0; i < 128; i += 4) {
                float4 v = __ldcv((const float4*)&slot[i]);
                acc[i+0] += v.x; acc[i+1] += v.y; acc[i+2] += v.z; acc[i+3] += v.w;
            }
            tile_epi_qk(acc, (t >> 3) * 128, (t & 7) * 256, wm, wn, lane, Ch, Cl);
        }
    }
    #undef LOAD_CHUNK
}

// ============== 2-CTA/SM stream-K fp16 1-pass GEMM (V and Wo) ================
// Tile 128x128. OUT==0: fp16 out (V, ldc=DM3). OUT==1: fp32 out (Wo, ldc=DM).
// Tiles may span >2 CTAs. Protocol: a CTA whose range ends mid-tile posts its
// partial (its final act). The CTA owning a tile's LAST chunk collects from
// LOWER-indexed posters (cta-1, cta-2, ...) until reaching the poster that
// covers the tile's first chunk. Waits point strictly down-index -> acyclic.
#define FSAH 0
#define FSBH (128*PITCHB)
#define FSTG (2*128*PITCHB)      // 20480
#define FACC 64

template<int OUT>
__global__ __launch_bounds__(256, 2) void gemm_f16(
    const unsigned short* __restrict__ A, const unsigned short* __restrict__ B,
    unsigned short* __restrict__ Ch, float* __restrict__ Cf, int ldc)
{
    extern __shared__ char smem[];
    const uint32_t sb0 = smem_u32(smem);
    const int tid  = threadIdx.x;
    const int lane = tid & 31;
    const int wm   = (tid >> 5) >> 2;
    const int wn   = (tid >> 5) & 3;
    const int cta  = blockIdx.x;
    const int G    = gridDim.x;

    const int total = 8192;            // 256 tiles (32m x 8n) x 32 chunks
    const int s = (int)(((long long)cta       * total) / G);
    const int e = (int)(((long long)(cta + 1) * total) / G);

    const uint32_t loff = (lane & 15) * PITCHB + ((lane >> 4) & 1) * 16;

    float acc[FACC];
    #pragma unroll
    for (int i = 0; i < FACC; i++) acc[i] = 0.0f;

    #define LOAD_CHUNK(c, stg) do { \
        int t_ = (c) >> 5; \
        int m0_ = (t_ >> 3) * 128, n0_ = (t_ & 7) * 128, k0_ = ((c) & 31) * 32; \
        const uint32_t sb_ = sb0 + (stg) * FSTG; \
        _Pragma("unroll") \
        for (int tt = 0; tt < 2; tt++) { \
            int idx = tid + tt*256; int r = idx >> 2, cc = idx & 3; \
            cp_async16(sb_ + FSAH + r*PITCHB + cc*16, A + (size_t)(m0_+r)*DM + k0_ + cc*8); \
            cp_async16(sb_ + FSBH + r*PITCHB + cc*16, B + (size_t)(n0_+r)*DM + k0_ + cc*8); \
        } \
        CP_COMMIT(); \
    } while (0)

    LOAD_CHUNK(s, 0);
    if (s + 1 < e) LOAD_CHUNK(s + 1, 1);
    int cur = 0;

    #pragma unroll 1
    for (int c = s; c < e; c++) {
        if (c + 1 < e) { CP_WAIT(1); } else { CP_WAIT(0); }
        __syncthreads();
        if (c + 2 < e) {
            int pf = cur - 1; if (pf < 0) pf = 2;
            LOAD_CHUNK(c + 2, pf);
        }

        const uint32_t sb = sb0 + cur * FSTG;
        cur = (cur == 2) ? 0 : cur + 1;

        #pragma unroll
        for (int kk = 0; kk < 2; kk++) {
            const uint32_t koff = kk * 32;
            uint32_t a[16], b[8];
            #pragma unroll
            for (int mt = 0; mt < 4; mt++)
                LDSM4(a + 4*mt, sb + FSAH + (wm*64 + mt*16)*PITCHB + loff + koff);
            #pragma unroll
            for (int p = 0; p < 2; p++)
                LDSM4(b + 4*p, sb + FSBH + (wn*32 + p*16)*PITCHB + loff + koff);
            #pragma unroll
            for (int mt = 0; mt < 4; mt++)
                #pragma unroll
                for (int p = 0; p < 2; p++) {
                    MMAF16(acc + (mt*4 + 2*p)*4,   a + 4*mt, b[4*p+0], b[4*p+2]);
                    MMAF16(acc + (mt*4 + 2*p+1)*4, a + 4*mt, b[4*p+1], b[4*p+3]);
                }
        }

        const int t = c >> 5;
        const int tile_first = t * 32;
        if ((c & 31) == 31) {
            if (tile_first < s) {
                // collect partials from LOWER-indexed posters of this tile
                int nb = cta - 1;
                while (true) {
                    if (tid == 0) {
                        while (atomicAdd(&g_flag[nb], 0) == 0) { __nanosleep(64); }
                        atomicExch(&g_flag[nb], 0);
                        __threadfence();
                    }
                    __syncthreads();
                    const float* slot = g_scr[nb] + (size_t)tid * FACC;
                    #pragma unroll
                    for (int i = 0; i < FACC; i += 4) {
                        float4 v = __ldcv((const float4*)&slot[i]);
                        acc[i+0] += v.x; acc[i+1] += v.y; acc[i+2] += v.z; acc[i+3] += v.w;
                    }
                    long long nbs = (long long)nb * total / G;   // start of nb's range
                    if (nbs <= (long long)tile_first) break;     // covered tile start
                    nb--;
                }
            }
            // write tile
            const int rbase = (t >> 3) * 128 + wm*64 + (lane >> 2);
            const int cbase = (t & 7) * 128 + wn*32 + (lane & 3) * 2;
            #pragma unroll
            for (int mt = 0; mt < 4; mt++)
                #pragma unroll
                for (int nt = 0; nt < 4; nt++) {
                    const float* q = acc + (mt*4 + nt)*4;
                    int row = rbase + mt*16, col = cbase + nt*8;
                    if (OUT == 0) {
                        *(uint32_t*)&Ch[(size_t)row * ldc + col]     = pack_h2(q[0], q[1]);
                        *(uint32_t*)&Ch[(size_t)(row+8) * ldc + col] = pack_h2(q[2], q[3]);
                    } else {
                        float2 v0; v0.x = q[0]; v0.y = q[1];
                        float2 v1; v1.x = q[2]; v1.y = q[3];
                        *(float2*)&Cf[(size_t)row * ldc + col]       = v0;
                        *(float2*)&Cf[(size_t)(row + 8) * ldc + col] = v1;
                    }
                }
            #pragma unroll
            for (int i = 0; i < FACC; i++) acc[i] = 0.0f;
        } else if (c == e - 1) {
            // range ends mid-tile: post partial (tile's last-chunk owner collects)
            float* slot = g_scr[cta] + (size_t)tid * FACC;
            #pragma unroll
            for (int i = 0; i < FACC; i += 4)
                *(float4*)&slot[i] = *(float4*)&acc[i];
            __threadfence();
            __syncthreads();
            if (tid == 0) atomicExch(&g_flag[cta], 1);
        }
    }
    #undef LOAD_CHUNK
}

// ============== MMA flash attention (BQ=64, 4 warps, 3 CTAs/SM) =============
#define BQ 64
#define BK 64
#define PB 144
#define SQ_H 0
#define SQ_L 9216
#define STG0 18432
#define STGSZ 27648
#define ATTN_SMEM (STG0 + 2*STGSZ)   // 73728

__global__ __launch_bounds__(128, 3) void attn_mma() {
    extern __shared__ char smc[];
    const uint32_t sb = smem_u32(smc);
    const int tid  = threadIdx.x;
    const int w    = tid >> 5;
    const int lane = tid & 31;
    const int bh = blockIdx.y, h = bh & 15, b = bh >> 4;
    const int q0 = blockIdx.x * BQ;
    const int rowbase = b * SEQ;

    const unsigned short* gxh = g_xh;
    const unsigned short* gxl = g_xl;

    #pragma unroll
    for (int t = 0; t < 8; t++) {
        int idx = tid + t*128;
        int arr = idx >> 9;
        int i2  = idx & 511;
        int r   = i2 >> 3, cc = i2 & 7;
        const unsigned short* src = (arr ? gxl : gxh)
            + (size_t)(rowbase + q0 + r) * DM3 + h*DH + cc*8;
        cp_async16(sb + (arr ? SQ_L : SQ_H) + r*PB + cc*16, src);
    }

    #define LOADKV(j) do { \
        const uint32_t st_ = sb + STG0 + ((j) & 1) * STGSZ; \
        const int kk0 = (j) * BK; \
        _Pragma("unroll") \
        for (int t = 0; t < 12; t++) { \
            int idx = tid + t*128; \
            int arr = idx >> 9; int i2 = idx & 511; \
            int r = i2 >> 3, cc = i2 & 7; \
            const unsigned short* srcp = (arr == 0) ? (gxh + 1024) \
                                       : (arr == 1) ? (gxl + 1024) : (gxh + 2048); \
            srcp += (size_t)(rowbase + kk0 + r) * DM3 + h*DH + cc*8; \
            cp_async16(st_ + arr*9216 + r*PB + cc*16, srcp); \
        } \
    } while (0)

    LOADKV(0);
    CP_COMMIT();

    const uint32_t loff = (lane & 15) * PB + (lane >> 4) * 16;
    uint32_t qfh[4][4], qfl[4][4];

    float o[8][4];
    #pragma unroll
    for (int dt = 0; dt < 8; dt++)
        #pragma unroll
        for (int q = 0; q < 4; q++) o[dt][q] = 0.0f;
    float m0r = -1e30f, m1r = -1e30f, l0r = 0.0f, l1r = 0.0f;

    const float* bt = g_bias + h * 4096;
    const int row0 = lane >> 2;
    const int col2 = (lane & 3) * 2;

    #pragma unroll 1
    for (int i = 0; i < SEQ/BK; i++) {
        if (i + 1 < SEQ/BK) LOADKV(i + 1);
        CP_COMMIT();
        CP_WAIT(1);
        __syncthreads();

        if (i == 0) {
            #pragma unroll
            for (int ks = 0; ks < 4; ks++) {
                LDSM4(qfh[ks], sb + SQ_H + w*16*PB + loff + ks*32);
                LDSM4(qfl[ks], sb + SQ_L + w*16*PB + loff + ks*32);
            }
        }

        const uint32_t st = sb + STG0 + (i & 1) * STGSZ;

        float s[8][4];
        #pragma unroll
        for (int nt = 0; nt < 8; nt++)
            #pragma unroll
            for (int q = 0; q < 4; q++) s[nt][q] = 0.0f;

        #pragma unroll
        for (int ks = 0; ks < 4; ks++) {
            #pragma unroll
            for (int np = 0; np < 4; np++) {
                uint32_t bh4[4], bl4[4];
                LDSM4(bh4, st + (np*16)*PB + loff + ks*32);
                LDSM4(bl4, st + 9216 + (np*16)*PB + loff + ks*32);
                MMA16816(s[2*np],   qfh[ks], bh4[0], bh4[2]);
                MMA16816(s[2*np+1], qfh[ks], bh4[1], bh4[3]);
                MMA16816(s[2*np],   qfl[ks], bh4[0], bh4[2]);
                MMA16816(s[2*np+1], qfl[ks], bh4[1], bh4[3]);
                MMA16816(s[2*np],   qfh[ks], bl4[0], bl4[2]);
                MMA16816(s[2*np+1], qfh[ks], bl4[1], bl4[3]);
            }
        }

        const float* bp0 = bt + 2048 + i*BK + col2 - (q0 + w*16 + row0);
        #pragma unroll
        for (int nt = 0; nt < 8; nt++) {
            s[nt][0] += __ldg(bp0 + nt*8);
            s[nt][1] += __ldg(bp0 + nt*8 + 1);
            s[nt][2] += __ldg(bp0 + nt*8 - 8);
            s[nt][3] += __ldg(bp0 + nt*8 - 7);
        }

        float t0 = -1e30f, t1 = -1e30f;
        #pragma unroll
        for (int nt = 0; nt < 8; nt++) {
            t0 = fmaxf(t0, fmaxf(s[nt][0], s[nt][1]));
            t1 = fmaxf(t1, fmaxf(s[nt][2], s[nt][3]));
        }
        t0 = fmaxf(t0, __shfl_xor_sync(0xffffffffu, t0, 1));
        t0 = fmaxf(t0, __shfl_xor_sync(0xffffffffu, t0, 2));
        t1 = fmaxf(t1, __shfl_xor_sync(0xffffffffu, t1, 1));
        t1 = fmaxf(t1, __shfl_xor_sync(0xffffffffu, t1, 2));
        float mn0 = fmaxf(m0r, t0), mn1 = fmaxf(m1r, t1);
        float a0 = expp(m0r - mn0), a1 = expp(m1r - mn1);
        m0r = mn0; m1r = mn1;

        float ps0 = 0.0f, ps1 = 0.0f;
        #pragma unroll
        for (int nt = 0; nt < 8; nt++) {
            s[nt][0] = expp(s[nt][0] - mn0);
            s[nt][1] = expp(s[nt][1] - mn0);
            s[nt][2] = expp(s[nt][2] - mn1);
            s[nt][3] = expp(s[nt][3] - mn1);
            ps0 += s[nt][0] + s[nt][1];
            ps1 += s[nt][2] + s[nt][3];
        }
        ps0 += __shfl_xor_sync(0xffffffffu, ps0, 1);
        ps0 += __shfl_xor_sync(0xffffffffu, ps0, 2);
        ps1 += __shfl_xor_sync(0xffffffffu, ps1, 1);
        ps1 += __shfl_xor_sync(0xffffffffu, ps1, 2);
        l0r = l0r * a0 + ps0;
        l1r = l1r * a1 + ps1;
        #pragma unroll
        for (int dt = 0; dt < 8; dt++) {
            o[dt][0] *= a0; o[dt][1] *= a0;
            o[dt][2] *= a1; o[dt][3] *= a1;
        }

        #pragma unroll
        for (int ks = 0; ks < 4; ks++) {
            uint32_t ph4[4];
            #pragma unroll
            for (int q = 0; q < 4; q++) {
                int nt = 2*ks + (q >> 1);
                ph4[q] = pack_h2(s[nt][(q & 1) * 2], s[nt][(q & 1) * 2 + 1]);
            }
            #pragma unroll
            for (int dp = 0; dp < 4; dp++) {
                uint32_t vh4[4];
                LDSM4T(vh4, st + 18432 + (ks*16 + (lane & 15))*PB + dp*32 + (lane >> 4)*16);
                MMAF16(o[2*dp],   ph4, vh4[0], vh4[1]);
                MMAF16(o[2*dp+1], ph4, vh4[2], vh4[3]);
            }
        }
        __syncthreads();
    }
    #undef LOADKV

    float inv0 = 1.0f / l0r, inv1 = 1.0f / l1r;
    unsigned short* oh = g_ah;
    const size_t gr0 = (size_t)(rowbase + q0 + w*16 + row0) * DM + h*DH;
    const size_t gr1 = gr0 + 8 * DM;
    #pragma unroll
    for (int dt = 0; dt < 8; dt++) {
        int col = dt*8 + col2;
        *(uint32_t*)&oh[gr0 + col] = pack_h2(o[dt][0]*inv0, o[dt][1]*inv0);
        *(uint32_t*)&oh[gr1 + col] = pack_h2(o[dt][2]*inv1, o[dt][3]*inv1);
    }
}

// ---------------- launch -----------------------------------------------------
extern "C" void kernel_launch(void* const* d_in, const int* in_sizes, int n_in,
                              void* d_out, int out_size) {
    const float* hidden = (const float*)d_in[0];
    const float* Wq     = (const float*)d_in[1];
    const float* Wk     = (const float*)d_in[2];
    const float* Wv     = (const float*)d_in[3];
    const float* Wo     = (const float*)d_in[4];
    const float* relb   = (const float*)d_in[5];
    float* out = (float*)d_out;

    void *phh, *phl, *phf, *pxh, *pxl, *pah, *pwh, *pwl;
    cudaGetSymbolAddress(&phh, g_hh);
    cudaGetSymbolAddress(&phl, g_hl);
    cudaGetSymbolAddress(&phf, g_hf);
    cudaGetSymbolAddress(&pxh, g_xh);
    cudaGetSymbolAddress(&pxl, g_xl);
    cudaGetSymbolAddress(&pah, g_ah);
    cudaGetSymbolAddress(&pwh, g_wh);
    cudaGetSymbolAddress(&pwl, g_wl);

    unsigned short* hh = (unsigned short*)phh;
    unsigned short* hl = (unsigned short*)phl;
    unsigned short* hf = (unsigned short*)phf;
    unsigned short* xh = (unsigned short*)pxh;
    unsigned short* xl = (unsigned short*)pxl;
    unsigned short* ah = (unsigned short*)pah;
    unsigned short* wh = (unsigned short*)pwh;
    unsigned short* wl = (unsigned short*)pwl;

    int dev = 0, sms = GRID_SK;
    cudaGetDevice(&dev);
    cudaDeviceGetAttribute(&sms, cudaDevAttrMultiProcessorCount, dev);
    int grid1 = (sms < GRID_SK) ? sms : GRID_SK;
    int grid2 = 2 * grid1;
    if (grid2 > GRID2) grid2 = GRID2;

    convert_split<<<(MROWS*DM/4)/256, 256>>>(hidden, hh, hl, hf);
    convert_w_all<<<dim3(DM/32, DM/32, 5), dim3(32, 8)>>>(Wq, Wk, Wv, Wo, relb);

    const int QK_SMEM = 3 * QSTG;    // 184320
    const int F_SMEM  = 3 * FSTG;    // 61440
    cudaFuncSetAttribute(gemm_qk, cudaFuncAttributeMaxDynamicSharedMemorySize, QK_SMEM);
    cudaFuncSetAttribute(gemm_f16<0>, cudaFuncAttributeMaxDynamicSharedMemorySize, F_SMEM);
    cudaFuncSetAttribute(gemm_f16<1>, cudaFuncAttributeMaxDynamicSharedMemorySize, F_SMEM);

    // QK projections: N=2048, bf16 3-pass, out bf16 hi/lo into xh/xl cols 0..2047
    gemm_qk<<<grid1, 256, QK_SMEM>>>(hh, hl, wh, wl, xh, xl);

    // V projection: fp16 1-pass, 2 CTAs/SM, out fp16 into xh cols 2048..3071
    gemm_f16<0><<<grid2, 256, F_SMEM>>>(hf, wh + 2*(size_t)DM*DM,
                                        xh + 2048, nullptr, DM3);

    cudaFuncSetAttribute(attn_mma, cudaFuncAttributeMaxDynamicSharedMemorySize, ATTN_SMEM);
    attn_mma<<<dim3(SEQ/BQ, BATCH*NH), 128, ATTN_SMEM>>>();

    // Wo: fp16 1-pass, 2 CTAs/SM, fp32 out
    gemm_f16<1><<<grid2, 256, F_SMEM>>>(ah, wh + 3*(size_t)DM*DM,
                                        nullptr, out, DM);
}

// round 15
// speedup vs baseline: 2.1334x; 2.1334x over previous
#include <cuda_runtime.h>
#include <cuda_bf16.h>
#include <cuda_fp16.h>
#include <math.h>
#include <stdint.h>

#define SEQ   2048
#define NH    16
#define DH    64
#define DM    1024
#define DM3   3072
#define BATCH 2
#define MROWS (BATCH*SEQ)   // 4096
#define GRID_SK 148

// ---------------- scratch (device globals; no allocations allowed) ----------
__device__ float g_bias[NH*4096];            // per-head bias vs (j-i)+2048
__device__ unsigned short g_hh[MROWS*DM];    // hidden bf16 hi
__device__ unsigned short g_hl[MROWS*DM];    // hidden bf16 lo
__device__ unsigned short g_hf[MROWS*DM];    // hidden fp16 single (V path)
__device__ unsigned short g_xh[MROWS*DM3];   // Q,K bf16-hi | V fp16   [row][3072]
__device__ unsigned short g_xl[MROWS*DM3];   // Q,K bf16-lo | (unused)
__device__ unsigned short g_ah[MROWS*DM];    // attn out fp16 single
__device__ unsigned short g_wh[4][DM*DM];    // W^T [n][k]: q,k bf16-hi; v,o fp16
__device__ unsigned short g_wl[4][DM*DM];    // q,k bf16-lo; v,o unused
__device__ float g_scr[GRID_SK][128*256];    // stream-K partials (QK: 256t*128; f512: 512t*32)
__device__ int   g_flag[GRID_SK+1];          // stream-K flags (self-resetting)

// ======================= helpers =============================================
__device__ __forceinline__ uint32_t smem_u32(const void* p) {
    uint32_t a;
    asm("{ .reg .u64 t; cvta.to.shared.u64 t, %1; cvt.u32.u64 %0, t; }" : "=r"(a) : "l"(p));
    return a;
}
__device__ __forceinline__ void cp_async16(uint32_t dst, const void* src) {
    asm volatile("cp.async.cg.shared.global [%0], [%1], 16;" :: "r"(dst), "l"(src));
}
#define CP_COMMIT() asm volatile("cp.async.commit_group;" ::: "memory")
#define CP_WAIT(N)  asm volatile("cp.async.wait_group %0;" :: "n"(N) : "memory")

#define LDSM4(r, addr) \
    asm volatile("ldmatrix.sync.aligned.m8n8.x4.shared.b16 {%0,%1,%2,%3}, [%4];" \
        : "=r"((r)[0]), "=r"((r)[1]), "=r"((r)[2]), "=r"((r)[3]) : "r"(addr))
#define LDSM4T(r, addr) \
    asm volatile("ldmatrix.sync.aligned.m8n8.x4.trans.shared.b16 {%0,%1,%2,%3}, [%4];" \
        : "=r"((r)[0]), "=r"((r)[1]), "=r"((r)[2]), "=r"((r)[3]) : "r"(addr))

#define MMA16816(c, a, b0, b1) \
    asm volatile("mma.sync.aligned.m16n8k16.row.col.f32.bf16.bf16.f32 " \
        "{%0,%1,%2,%3}, {%4,%5,%6,%7}, {%8,%9}, {%0,%1,%2,%3};" \
        : "+f"((c)[0]), "+f"((c)[1]), "+f"((c)[2]), "+f"((c)[3]) \
        : "r"((a)[0]), "r"((a)[1]), "r"((a)[2]), "r"((a)[3]), "r"(b0), "r"(b1))

#define MMAF16(c, a, b0, b1) \
    asm volatile("mma.sync.aligned.m16n8k16.row.col.f32.f16.f16.f32 " \
        "{%0,%1,%2,%3}, {%4,%5,%6,%7}, {%8,%9}, {%0,%1,%2,%3};" \
        : "+f"((c)[0]), "+f"((c)[1]), "+f"((c)[2]), "+f"((c)[3]) \
        : "r"((a)[0]), "r"((a)[1]), "r"((a)[2]), "r"((a)[3]), "r"(b0), "r"(b1))

__device__ __forceinline__ uint32_t pack_bf2(float x, float y) {
    __nv_bfloat162 t = __floats2bfloat162_rn(x, y);
    return *(uint32_t*)&t;
}
__device__ __forceinline__ float2 unpack_bf2(uint32_t u) {
    __nv_bfloat162 t = *(__nv_bfloat162*)&u;
    return __bfloat1622float2(t);
}
__device__ __forceinline__ uint32_t pack_h2(float x, float y) {
    __half2 t = __floats2half2_rn(x, y);
    return *(uint32_t*)&t;
}

// fast exp on the FMA pipe (args <= 0; clamp keeps scale exponent valid)
__device__ __forceinline__ float expp(float x) {
    x = fmaxf(x, -80.0f);
    float y = x * 1.4426950408889634f;
    float t = y + 12582912.0f;
    int   n = __float_as_int(t) - 0x4B400000;
    float f = y - (t - 12582912.0f);
    float g = f * 0.6931471805599453f;
    float p = fmaf(g, 0.008333333f, 0.041666668f);
    p = fmaf(p, g, 0.16666667f);
    p = fmaf(p, g, 0.5f);
    p = fmaf(p, g, 1.0f);
    p = fmaf(p, g, 1.0f);
    return p * __int_as_float((n + 127) << 23);
}

// ------ fp32 -> bf16 hi/lo split + fp16 single (elementwise) ----------------
__global__ void convert_split(const float* __restrict__ x,
                              unsigned short* __restrict__ oh,
                              unsigned short* __restrict__ ol,
                              unsigned short* __restrict__ of) {
    int i = blockIdx.x * blockDim.x + threadIdx.x;
    float4 v = ((const float4*)x)[i];
    uint32_t h01 = pack_bf2(v.x, v.y);
    uint32_t h23 = pack_bf2(v.z, v.w);
    float2 f01 = unpack_bf2(h01);
    float2 f23 = unpack_bf2(h23);
    uint32_t* ph = (uint32_t*)(oh + 4*(size_t)i);
    uint32_t* pl = (uint32_t*)(ol + 4*(size_t)i);
    uint32_t* pf = (uint32_t*)(of + 4*(size_t)i);
    ph[0] = h01; ph[1] = h23;
    pl[0] = pack_bf2(v.x - f01.x, v.y - f01.y);
    pl[1] = pack_bf2(v.z - f23.x, v.w - f23.y);
    pf[0] = pack_h2(v.x, v.y);
    pf[1] = pack_h2(v.z, v.w);
}

// ---- W converts (z=0..3) + bias table (z=4), one launch ---------------------
__global__ void convert_w_all(const float* __restrict__ W0, const float* __restrict__ W1,
                              const float* __restrict__ W2, const float* __restrict__ W3,
                              const float* __restrict__ rel_bias) {
    __shared__ float t[32][33];
    int z = blockIdx.z;
    int tx = threadIdx.x, ty = threadIdx.y;
    if (z == 4) {
        if (blockIdx.y != 0 || blockIdx.x >= NH) return;
        int h = blockIdx.x;
        int tid = ty * 32 + tx;
        for (int i = tid; i < 4096; i += 256) {
            int delta = i - 2048;
            int rb = (delta > 0) ? 16 : 0;
            int ar = delta < 0 ? -delta : delta;
            int bucket;
            if (ar < 8) {
                bucket = rb + ar;
            } else {
                int l = 8 + (int)(2.0f * log2f((float)ar * 0.125f));
                bucket = rb + (l > 15 ? 15 : l);
            }
            g_bias[h*4096 + i] = rel_bias[bucket*NH + h];
        }
        return;
    }
    const float* W = (z == 0) ? W0 : (z == 1) ? W1 : (z == 2) ? W2 : W3;
    unsigned short* oh = (unsigned short*)g_wh + (size_t)z * DM * DM;
    unsigned short* ol = (unsigned short*)g_wl + (size_t)z * DM * DM;
    int n0 = blockIdx.x * 32, k0 = blockIdx.y * 32;
    #pragma unroll
    for (int j = 0; j < 32; j += 8)
        t[ty + j][tx] = W[(size_t)(k0 + ty + j) * DM + n0 + tx];
    __syncthreads();
    #pragma unroll
    for (int j = 0; j < 32; j += 8) {
        float v = t[tx][ty + j];
        size_t o = (size_t)(n0 + ty + j) * DM + k0 + tx;
        if (z >= 2) {
            __half h = __float2half_rn(v);
            oh[o] = *(unsigned short*)&h;
        } else {
            __nv_bfloat16 h = __float2bfloat16_rn(v);
            oh[o] = *(unsigned short*)&h;
            __nv_bfloat16 l = __float2bfloat16_rn(v - __bfloat162float(h));
            ol[o] = *(unsigned short*)&l;
        }
    }
}

// ============== stream-K QK GEMM (bf16 3-pass, out bf16 hi/lo) ===============
#define PITCHB 80

__device__ __forceinline__ void tile_epi_qk(const float* acc, int m0, int n0,
                                            int wm, int wn, int lane,
                                            unsigned short* Ch, unsigned short* Cl)
{
    const int rbase = m0 + wm*64 + (lane >> 2);
    const int cbase = n0 + wn*64 + (lane & 3) * 2;
    #pragma unroll
    for (int mt = 0; mt < 4; mt++) {
        #pragma unroll
        for (int nt = 0; nt < 8; nt++) {
            const float* q = acc + (mt*8 + nt)*4;
            int row = rbase + mt*16;
            int col = cbase + nt*8;
            uint32_t h0 = pack_bf2(q[0], q[1]);
            float2 f0 = unpack_bf2(h0);
            *(uint32_t*)&Ch[(size_t)row * DM3 + col] = h0;
            *(uint32_t*)&Cl[(size_t)row * DM3 + col] = pack_bf2(q[0]-f0.x, q[1]-f0.y);
            uint32_t h1 = pack_bf2(q[2], q[3]);
            float2 f1 = unpack_bf2(h1);
            *(uint32_t*)&Ch[(size_t)(row+8) * DM3 + col] = h1;
            *(uint32_t*)&Cl[(size_t)(row+8) * DM3 + col] = pack_bf2(q[2]-f1.x, q[3]-f1.y);
        }
    }
}

#define QSAH 0
#define QSAL (128*PITCHB)
#define QSBH (2*128*PITCHB)
#define QSBL (QSBH + 256*PITCHB)
#define QSTG (QSBH + 2*256*PITCHB)

__global__ __launch_bounds__(256, 1) void gemm_qk(
    const unsigned short* __restrict__ Ah, const unsigned short* __restrict__ Al,
    const unsigned short* __restrict__ Bh, const unsigned short* __restrict__ Bl,
    unsigned short* __restrict__ Ch, unsigned short* __restrict__ Cl)
{
    extern __shared__ char smem[];
    const uint32_t sb0 = smem_u32(smem);
    const int tid  = threadIdx.x;
    const int lane = tid & 31;
    const int wm   = (tid >> 5) >> 2;
    const int wn   = (tid >> 5) & 3;
    const int cta  = blockIdx.x;
    const int G    = gridDim.x;

    const int total = 8192;           // 256 tiles (32m x 8n) x 32 chunks
    const int s = (int)(((long long)cta       * total) / G);
    const int e = (int)(((long long)(cta + 1) * total) / G);

    const uint32_t loff = (lane & 15) * PITCHB + ((lane >> 4) & 1) * 16;

    float acc[128];
    #pragma unroll
    for (int i = 0; i < 128; i++) acc[i] = 0.0f;

    #define LOAD_CHUNK(c, stg) do { \
        int t_  = (c) >> 5; \
        int m0_ = (t_ >> 3) * 128, n0_ = (t_ & 7) * 256, k0_ = ((c) & 31) * 32; \
        const uint32_t sb_ = sb0 + (stg) * QSTG; \
        _Pragma("unroll") \
        for (int tt = 0; tt < 2; tt++) { \
            int idx = tid + tt*256; int r = idx >> 2, cc = idx & 3; \
            cp_async16(sb_ + QSAH + r*PITCHB + cc*16, Ah + (size_t)(m0_+r)*DM + k0_ + cc*8); \
            cp_async16(sb_ + QSAL + r*PITCHB + cc*16, Al + (size_t)(m0_+r)*DM + k0_ + cc*8); \
        } \
        _Pragma("unroll") \
        for (int tt = 0; tt < 4; tt++) { \
            int idx = tid + tt*256; int r = idx >> 2, cc = idx & 3; \
            cp_async16(sb_ + QSBH + r*PITCHB + cc*16, Bh + (size_t)(n0_+r)*DM + k0_ + cc*8); \
            cp_async16(sb_ + QSBL + r*PITCHB + cc*16, Bl + (size_t)(n0_+r)*DM + k0_ + cc*8); \
        } \
        CP_COMMIT(); \
    } while (0)

    LOAD_CHUNK(s, 0);
    if (s + 1 < e) LOAD_CHUNK(s + 1, 1);
    int cur = 0;

    #pragma unroll 1
    for (int c = s; c < e; c++) {
        if (c + 1 < e) { CP_WAIT(1); } else { CP_WAIT(0); }
        __syncthreads();
        if (c + 2 < e) {
            int pf = cur - 1; if (pf < 0) pf = 2;
            LOAD_CHUNK(c + 2, pf);
        }

        const uint32_t sb = sb0 + cur * QSTG;
        cur = (cur == 2) ? 0 : cur + 1;

        #pragma unroll
        for (int kk = 0; kk < 2; kk++) {
            const uint32_t koff = kk * 32;
            uint32_t a[16], a2[16], bhf[16], blf[16];
            #pragma unroll
            for (int mt = 0; mt < 4; mt++)
                LDSM4(a + 4*mt,  sb + QSAH + (wm*64 + mt*16)*PITCHB + loff + koff);
            #pragma unroll
            for (int p = 0; p < 4; p++)
                LDSM4(bhf + 4*p, sb + QSBH + (wn*64 + p*16)*PITCHB + loff + koff);
            #pragma unroll
            for (int mt = 0; mt < 4; mt++)
                LDSM4(a2 + 4*mt, sb + QSAL + (wm*64 + mt*16)*PITCHB + loff + koff);
            #pragma unroll
            for (int p = 0; p < 4; p++)
                LDSM4(blf + 4*p, sb + QSBL + (wn*64 + p*16)*PITCHB + loff + koff);
            #pragma unroll
            for (int mt = 0; mt < 4; mt++)
                #pragma unroll
                for (int p = 0; p < 4; p++) {
                    MMA16816(acc + (mt*8 + 2*p)*4,   a + 4*mt, bhf[4*p+0], bhf[4*p+2]);
                    MMA16816(acc + (mt*8 + 2*p+1)*4, a + 4*mt, bhf[4*p+1], bhf[4*p+3]);
                }
            #pragma unroll
            for (int mt = 0; mt < 4; mt++)
                #pragma unroll
                for (int p = 0; p < 4; p++) {
                    MMA16816(acc + (mt*8 + 2*p)*4,   a2 + 4*mt, bhf[4*p+0], bhf[4*p+2]);
                    MMA16816(acc + (mt*8 + 2*p+1)*4, a2 + 4*mt, bhf[4*p+1], bhf[4*p+3]);
                }
            #pragma unroll
            for (int mt = 0; mt < 4; mt++)
                #pragma unroll
                for (int p = 0; p < 4; p++) {
                    MMA16816(acc + (mt*8 + 2*p)*4,   a + 4*mt, blf[4*p+0], blf[4*p+2]);
                    MMA16816(acc + (mt*8 + 2*p+1)*4, a + 4*mt, blf[4*p+1], blf[4*p+3]);
                }
        }

        const int t = c >> 5;
        if ((c & 31) == 31) {
            if (t * 32 >= s) {
                tile_epi_qk(acc, (t >> 3) * 128, (t & 7) * 256, wm, wn, lane, Ch, Cl);
            } else {
                float* slot = g_scr[cta] + (size_t)tid * 128;
                #pragma unroll
                for (int i = 0; i < 128; i += 4)
                    *(float4*)&slot[i] = *(float4*)&acc[i];
                __threadfence();
                __syncthreads();
                if (tid == 0) atomicExch(&g_flag[cta], 1);
            }
            #pragma unroll
            for (int i = 0; i < 128; i++) acc[i] = 0.0f;
        } else if (c == e - 1) {
            if (tid == 0) {
                while (atomicAdd(&g_flag[cta + 1], 0) == 0) { __nanosleep(64); }
                atomicExch(&g_flag[cta + 1], 0);
                __threadfence();
            }
            __syncthreads();
            const float* slot = g_scr[cta + 1] + (size_t)tid * 128;
            #pragma unroll
            for (int i = 0; i < 128; i += 4) {
                float4 v = __ldcv((const float4*)&slot[i]);
                acc[i+0] += v.x; acc[i+1] += v.y; acc[i+2] += v.z; acc[i+3] += v.w;
            }
            tile_epi_qk(acc, (t >> 3) * 128, (t & 7) * 256, wm, wn, lane, Ch, Cl);
        }
    }
    #undef LOAD_CHUNK
}

// ======== 512-thread stream-K fp16 1-pass GEMM (V and Wo), 1 CTA/SM ========
// Tile 128x128, 16 warps (4m x 4n), warp tile 32x32, 4 warps/SMSP.
// Round-11 protocol: grid=148 -> 55.4 chunks/CTA -> tiles span <=2 CTAs.
// Tail-owner posts its partial at its FIRST tile boundary (early); head
// (range ends mid-tile) waits on flag[cta+1].
#define FSAH 0
#define FSBH (128*PITCHB)
#define FSTG (2*128*PITCHB)      // 20480
#define FACC 32

template<int OUT>
__global__ __launch_bounds__(512, 1) void gemm_f512(
    const unsigned short* __restrict__ A, const unsigned short* __restrict__ B,
    unsigned short* __restrict__ Ch, float* __restrict__ Cf, int ldc)
{
    extern __shared__ char smem[];
    const uint32_t sb0 = smem_u32(smem);
    const int tid  = threadIdx.x;           // 0..511
    const int lane = tid & 31;
    const int wid  = tid >> 5;               // 0..15
    const int wm   = wid >> 2;               // 0..3
    const int wn   = wid & 3;                // 0..3
    const int cta  = blockIdx.x;
    const int G    = gridDim.x;

    const int total = 8192;                  // 256 tiles (32m x 8n) x 32 chunks
    const int s = (int)(((long long)cta       * total) / G);
    const int e = (int)(((long long)(cta + 1) * total) / G);

    const uint32_t loff = (lane & 15) * PITCHB + ((lane >> 4) & 1) * 16;

    float acc[FACC];
    #pragma unroll
    for (int i = 0; i < FACC; i++) acc[i] = 0.0f;

    #define LOAD_CHUNK(c, stg) do { \
        int t_ = (c) >> 5; \
        int m0_ = (t_ >> 3) * 128, n0_ = (t_ & 7) * 128, k0_ = ((c) & 31) * 32; \
        const uint32_t sb_ = sb0 + (stg) * FSTG; \
        { \
            int r = tid >> 2, cc = tid & 3; \
            cp_async16(sb_ + FSAH + r*PITCHB + cc*16, A + (size_t)(m0_+r)*DM + k0_ + cc*8); \
            cp_async16(sb_ + FSBH + r*PITCHB + cc*16, B + (size_t)(n0_+r)*DM + k0_ + cc*8); \
        } \
        CP_COMMIT(); \
    } while (0)

    LOAD_CHUNK(s, 0);
    if (s + 1 < e) LOAD_CHUNK(s + 1, 1);
    int cur = 0;

    #pragma unroll 1
    for (int c = s; c < e; c++) {
        if (c + 1 < e) { CP_WAIT(1); } else { CP_WAIT(0); }
        __syncthreads();
        if (c + 2 < e) {
            int pf = cur - 1; if (pf < 0) pf = 2;
            LOAD_CHUNK(c + 2, pf);
        }

        const uint32_t sb = sb0 + cur * FSTG;
        cur = (cur == 2) ? 0 : cur + 1;

        #pragma unroll
        for (int kk = 0; kk < 2; kk++) {
            const uint32_t koff = kk * 32;
            uint32_t a[8], b[8];
            LDSM4(a,     sb + FSAH + (wm*32)*PITCHB      + loff + koff);
            LDSM4(a + 4, sb + FSAH + (wm*32 + 16)*PITCHB + loff + koff);
            LDSM4(b,     sb + FSBH + (wn*32)*PITCHB      + loff + koff);
            LDSM4(b + 4, sb + FSBH + (wn*32 + 16)*PITCHB + loff + koff);
            #pragma unroll
            for (int mt = 0; mt < 2; mt++)
                #pragma unroll
                for (int p = 0; p < 2; p++) {
                    MMAF16(acc + (mt*4 + 2*p)*4,   a + 4*mt, b[4*p+0], b[4*p+2]);
                    MMAF16(acc + (mt*4 + 2*p+1)*4, a + 4*mt, b[4*p+1], b[4*p+3]);
                }
        }

        const int t = c >> 5;
        if ((c & 31) == 31) {
            if (t * 32 >= s) {
                // full tile owned: write out
                const int rbase = (t >> 3) * 128 + wm*32 + (lane >> 2);
                const int cbase = (t & 7) * 128 + wn*32 + (lane & 3) * 2;
                #pragma unroll
                for (int mt = 0; mt < 2; mt++)
                    #pragma unroll
                    for (int nt = 0; nt < 4; nt++) {
                        const float* q = acc + (mt*4 + nt)*4;
                        int row = rbase + mt*16, col = cbase + nt*8;
                        if (OUT == 0) {
                            *(uint32_t*)&Ch[(size_t)row * ldc + col]     = pack_h2(q[0], q[1]);
                            *(uint32_t*)&Ch[(size_t)(row+8) * ldc + col] = pack_h2(q[2], q[3]);
                        } else {
                            float2 v0; v0.x = q[0]; v0.y = q[1];
                            float2 v1; v1.x = q[2]; v1.y = q[3];
                            *(float2*)&Cf[(size_t)row * ldc + col]       = v0;
                            *(float2*)&Cf[(size_t)(row + 8) * ldc + col] = v1;
                        }
                    }
            } else {
                // tail of split tile: post partial EARLY (first tile of range)
                float* slot = g_scr[cta] + (size_t)tid * FACC;
                #pragma unroll
                for (int i = 0; i < FACC; i += 4)
                    *(float4*)&slot[i] = *(float4*)&acc[i];
                __threadfence();
                __syncthreads();
                if (tid == 0) atomicExch(&g_flag[cta], 1);
            }
            #pragma unroll
            for (int i = 0; i < FACC; i++) acc[i] = 0.0f;
        } else if (c == e - 1) {
            // head of split tile: wait for cta+1's early post, add, write
            if (tid == 0) {
                while (atomicAdd(&g_flag[cta + 1], 0) == 0) { __nanosleep(64); }
                atomicExch(&g_flag[cta + 1], 0);
                __threadfence();
            }
            __syncthreads();
            const float* slot = g_scr[cta + 1] + (size_t)tid * FACC;
            #pragma unroll
            for (int i = 0; i < FACC; i += 4) {
                float4 v = __ldcv((const float4*)&slot[i]);
                acc[i+0] += v.x; acc[i+1] += v.y; acc[i+2] += v.z; acc[i+3] += v.w;
            }
            const int rbase = (t >> 3) * 128 + wm*32 + (lane >> 2);
            const int cbase = (t & 7) * 128 + wn*32 + (lane & 3) * 2;
            #pragma unroll
            for (int mt = 0; mt < 2; mt++)
                #pragma unroll
                for (int nt = 0; nt < 4; nt++) {
                    const float* q = acc + (mt*4 + nt)*4;
                    int row = rbase + mt*16, col = cbase + nt*8;
                    if (OUT == 0) {
                        *(uint32_t*)&Ch[(size_t)row * ldc + col]     = pack_h2(q[0], q[1]);
                        *(uint32_t*)&Ch[(size_t)(row+8) * ldc + col] = pack_h2(q[2], q[3]);
                    } else {
                        float2 v0; v0.x = q[0]; v0.y = q[1];
                        float2 v1; v1.x = q[2]; v1.y = q[3];
                        *(float2*)&Cf[(size_t)row * ldc + col]       = v0;
                        *(float2*)&Cf[(size_t)(row + 8) * ldc + col] = v1;
                    }
                }
        }
    }
    #undef LOAD_CHUNK
}

// ============== MMA flash attention (BQ=64, 4 warps, 3 CTAs/SM) =============
#define BQ 64
#define BK 64
#define PB 144
#define SQ_H 0
#define SQ_L 9216
#define STG0 18432
#define STGSZ 27648
#define ATTN_SMEM (STG0 + 2*STGSZ)   // 73728

__global__ __launch_bounds__(128, 3) void attn_mma() {
    extern __shared__ char smc[];
    const uint32_t sb = smem_u32(smc);
    const int tid  = threadIdx.x;
    const int w    = tid >> 5;
    const int lane = tid & 31;
    const int bh = blockIdx.y, h = bh & 15, b = bh >> 4;
    const int q0 = blockIdx.x * BQ;
    const int rowbase = b * SEQ;

    const unsigned short* gxh = g_xh;
    const unsigned short* gxl = g_xl;

    #pragma unroll
    for (int t = 0; t < 8; t++) {
        int idx = tid + t*128;
        int arr = idx >> 9;
        int i2  = idx & 511;
        int r   = i2 >> 3, cc = i2 & 7;
        const unsigned short* src = (arr ? gxl : gxh)
            + (size_t)(rowbase + q0 + r) * DM3 + h*DH + cc*8;
        cp_async16(sb + (arr ? SQ_L : SQ_H) + r*PB + cc*16, src);
    }

    #define LOADKV(j) do { \
        const uint32_t st_ = sb + STG0 + ((j) & 1) * STGSZ; \
        const int kk0 = (j) * BK; \
        _Pragma("unroll") \
        for (int t = 0; t < 12; t++) { \
            int idx = tid + t*128; \
            int arr = idx >> 9; int i2 = idx & 511; \
            int r = i2 >> 3, cc = i2 & 7; \
            const unsigned short* srcp = (arr == 0) ? (gxh + 1024) \
                                       : (arr == 1) ? (gxl + 1024) : (gxh + 2048); \
            srcp += (size_t)(rowbase + kk0 + r) * DM3 + h*DH + cc*8; \
            cp_async16(st_ + arr*9216 + r*PB + cc*16, srcp); \
        } \
    } while (0)

    LOADKV(0);
    CP_COMMIT();

    const uint32_t loff = (lane & 15) * PB + (lane >> 4) * 16;
    uint32_t qfh[4][4], qfl[4][4];

    float o[8][4];
    #pragma unroll
    for (int dt = 0; dt < 8; dt++)
        #pragma unroll
        for (int q = 0; q < 4; q++) o[dt][q] = 0.0f;
    float m0r = -1e30f, m1r = -1e30f, l0r = 0.0f, l1r = 0.0f;

    const float* bt = g_bias + h * 4096;
    const int row0 = lane >> 2;
    const int col2 = (lane & 3) * 2;

    #pragma unroll 1
    for (int i = 0; i < SEQ/BK; i++) {
        if (i + 1 < SEQ/BK) LOADKV(i + 1);
        CP_COMMIT();
        CP_WAIT(1);
        __syncthreads();

        if (i == 0) {
            #pragma unroll
            for (int ks = 0; ks < 4; ks++) {
                LDSM4(qfh[ks], sb + SQ_H + w*16*PB + loff + ks*32);
                LDSM4(qfl[ks], sb + SQ_L + w*16*PB + loff + ks*32);
            }
        }

        const uint32_t st = sb + STG0 + (i & 1) * STGSZ;

        float s[8][4];
        #pragma unroll
        for (int nt = 0; nt < 8; nt++)
            #pragma unroll
            for (int q = 0; q < 4; q++) s[nt][q] = 0.0f;

        #pragma unroll
        for (int ks = 0; ks < 4; ks++) {
            #pragma unroll
            for (int np = 0; np < 4; np++) {
                uint32_t bh4[4], bl4[4];
                LDSM4(bh4, st + (np*16)*PB + loff + ks*32);
                LDSM4(bl4, st + 9216 + (np*16)*PB + loff + ks*32);
                MMA16816(s[2*np],   qfh[ks], bh4[0], bh4[2]);
                MMA16816(s[2*np+1], qfh[ks], bh4[1], bh4[3]);
                MMA16816(s[2*np],   qfl[ks], bh4[0], bh4[2]);
                MMA16816(s[2*np+1], qfl[ks], bh4[1], bh4[3]);
                MMA16816(s[2*np],   qfh[ks], bl4[0], bl4[2]);
                MMA16816(s[2*np+1], qfh[ks], bl4[1], bl4[3]);
            }
        }

        const float* bp0 = bt + 2048 + i*BK + col2 - (q0 + w*16 + row0);
        #pragma unroll
        for (int nt = 0; nt < 8; nt++) {
            s[nt][0] += __ldg(bp0 + nt*8);
            s[nt][1] += __ldg(bp0 + nt*8 + 1);
            s[nt][2] += __ldg(bp0 + nt*8 - 8);
            s[nt][3] += __ldg(bp0 + nt*8 - 7);
        }

        float t0 = -1e30f, t1 = -1e30f;
        #pragma unroll
        for (int nt = 0; nt < 8; nt++) {
            t0 = fmaxf(t0, fmaxf(s[nt][0], s[nt][1]));
            t1 = fmaxf(t1, fmaxf(s[nt][2], s[nt][3]));
        }
        t0 = fmaxf(t0, __shfl_xor_sync(0xffffffffu, t0, 1));
        t0 = fmaxf(t0, __shfl_xor_sync(0xffffffffu, t0, 2));
        t1 = fmaxf(t1, __shfl_xor_sync(0xffffffffu, t1, 1));
        t1 = fmaxf(t1, __shfl_xor_sync(0xffffffffu, t1, 2));
        float mn0 = fmaxf(m0r, t0), mn1 = fmaxf(m1r, t1);
        float a0 = expp(m0r - mn0), a1 = expp(m1r - mn1);
        m0r = mn0; m1r = mn1;

        float ps0 = 0.0f, ps1 = 0.0f;
        #pragma unroll
        for (int nt = 0; nt < 8; nt++) {
            s[nt][0] = expp(s[nt][0] - mn0);
            s[nt][1] = expp(s[nt][1] - mn0);
            s[nt][2] = expp(s[nt][2] - mn1);
            s[nt][3] = expp(s[nt][3] - mn1);
            ps0 += s[nt][0] + s[nt][1];
            ps1 += s[nt][2] + s[nt][3];
        }
        ps0 += __shfl_xor_sync(0xffffffffu, ps0, 1);
        ps0 += __shfl_xor_sync(0xffffffffu, ps0, 2);
        ps1 += __shfl_xor_sync(0xffffffffu, ps1, 1);
        ps1 += __shfl_xor_sync(0xffffffffu, ps1, 2);
        l0r = l0r * a0 + ps0;
        l1r = l1r * a1 + ps1;
        #pragma unroll
        for (int dt = 0; dt < 8; dt++) {
            o[dt][0] *= a0; o[dt][1] *= a0;
            o[dt][2] *= a1; o[dt][3] *= a1;
        }

        #pragma unroll
        for (int ks = 0; ks < 4; ks++) {
            uint32_t ph4[4];
            #pragma unroll
            for (int q = 0; q < 4; q++) {
                int nt = 2*ks + (q >> 1);
                ph4[q] = pack_h2(s[nt][(q & 1) * 2], s[nt][(q & 1) * 2 + 1]);
            }
            #pragma unroll
            for (int dp = 0; dp < 4; dp++) {
                uint32_t vh4[4];
                LDSM4T(vh4, st + 18432 + (ks*16 + (lane & 15))*PB + dp*32 + (lane >> 4)*16);
                MMAF16(o[2*dp],   ph4, vh4[0], vh4[1]);
                MMAF16(o[2*dp+1], ph4, vh4[2], vh4[3]);
            }
        }
        __syncthreads();
    }
    #undef LOADKV

    float inv0 = 1.0f / l0r, inv1 = 1.0f / l1r;
    unsigned short* oh = g_ah;
    const size_t gr0 = (size_t)(rowbase + q0 + w*16 + row0) * DM + h*DH;
    const size_t gr1 = gr0 + 8 * DM;
    #pragma unroll
    for (int dt = 0; dt < 8; dt++) {
        int col = dt*8 + col2;
        *(uint32_t*)&oh[gr0 + col] = pack_h2(o[dt][0]*inv0, o[dt][1]*inv0);
        *(uint32_t*)&oh[gr1 + col] = pack_h2(o[dt][2]*inv1, o[dt][3]*inv1);
    }
}

// ---------------- launch -----------------------------------------------------
extern "C" void kernel_launch(void* const* d_in, const int* in_sizes, int n_in,
                              void* d_out, int out_size) {
    const float* hidden = (const float*)d_in[0];
    const float* Wq     = (const float*)d_in[1];
    const float* Wk     = (const float*)d_in[2];
    const float* Wv     = (const float*)d_in[3];
    const float* Wo     = (const float*)d_in[4];
    const float* relb   = (const float*)d_in[5];
    float* out = (float*)d_out;

    void *phh, *phl, *phf, *pxh, *pxl, *pah, *pwh, *pwl;
    cudaGetSymbolAddress(&phh, g_hh);
    cudaGetSymbolAddress(&phl, g_hl);
    cudaGetSymbolAddress(&phf, g_hf);
    cudaGetSymbolAddress(&pxh, g_xh);
    cudaGetSymbolAddress(&pxl, g_xl);
    cudaGetSymbolAddress(&pah, g_ah);
    cudaGetSymbolAddress(&pwh, g_wh);
    cudaGetSymbolAddress(&pwl, g_wl);

    unsigned short* hh = (unsigned short*)phh;
    unsigned short* hl = (unsigned short*)phl;
    unsigned short* hf = (unsigned short*)phf;
    unsigned short* xh = (unsigned short*)pxh;
    unsigned short* xl = (unsigned short*)pxl;
    unsigned short* ah = (unsigned short*)pah;
    unsigned short* wh = (unsigned short*)pwh;
    unsigned short* wl = (unsigned short*)pwl;

    int dev = 0, sms = GRID_SK;
    cudaGetDevice(&dev);
    cudaDeviceGetAttribute(&sms, cudaDevAttrMultiProcessorCount, dev);
    int grid1 = (sms < GRID_SK) ? sms : GRID_SK;

    convert_split<<<(MROWS*DM/4)/256, 256>>>(hidden, hh, hl, hf);
    convert_w_all<<<dim3(DM/32, DM/32, 5), dim3(32, 8)>>>(Wq, Wk, Wv, Wo, relb);

    const int QK_SMEM = 3 * QSTG;    // 184320
    const int F_SMEM  = 3 * FSTG;    // 61440
    cudaFuncSetAttribute(gemm_qk, cudaFuncAttributeMaxDynamicSharedMemorySize, QK_SMEM);
    cudaFuncSetAttribute(gemm_f512<0>, cudaFuncAttributeMaxDynamicSharedMemorySize, F_SMEM);
    cudaFuncSetAttribute(gemm_f512<1>, cudaFuncAttributeMaxDynamicSharedMemorySize, F_SMEM);

    // QK projections: N=2048, bf16 3-pass, out bf16 hi/lo into xh/xl cols 0..2047
    gemm_qk<<<grid1, 256, QK_SMEM>>>(hh, hl, wh, wl, xh, xl);

    // V projection: fp16 1-pass, 512 threads, out fp16 into xh cols 2048..3071
    gemm_f512<0><<<grid1, 512, F_SMEM>>>(hf, wh + 2*(size_t)DM*DM,
                                         xh + 2048, nullptr, DM3);

    cudaFuncSetAttribute(attn_mma, cudaFuncAttributeMaxDynamicSharedMemorySize, ATTN_SMEM);
    attn_mma<<<dim3(SEQ/BQ, BATCH*NH), 128, ATTN_SMEM>>>();

    // Wo: fp16 1-pass, 512 threads, fp32 out
    gemm_f512<1><<<grid1, 512, F_SMEM>>>(ah, wh + 3*(size_t)DM*DM,
                                         nullptr, out, DM);
}

// round 16
// speedup vs baseline: 2.1727x; 1.0184x over previous
#include <cuda_runtime.h>
#include <cuda_bf16.h>
#include <cuda_fp16.h>
#include <math.h>
#include <stdint.h>

#define SEQ   2048
#define NH    16
#define DH    64
#define DM    1024
#define DM3   3072
#define BATCH 2
#define MROWS (BATCH*SEQ)   // 4096
#define GRID_SK 148

// ---------------- scratch (device globals; no allocations allowed) ----------
__device__ float g_bias[NH*4096];            // per-head bias vs (j-i)+2048
__device__ unsigned short g_hh[MROWS*DM];    // hidden bf16 hi
__device__ unsigned short g_hl[MROWS*DM];    // hidden bf16 lo
__device__ unsigned short g_hf[MROWS*DM];    // hidden fp16 single (V path)
__device__ unsigned short g_xh[MROWS*DM3];   // Q,K bf16-hi | V fp16   [row][3072]
__device__ unsigned short g_xl[MROWS*DM3];   // Q,K bf16-lo | (unused)
__device__ unsigned short g_ah[MROWS*DM];    // attn out fp16 single
__device__ unsigned short g_wh[4][DM*DM];    // W^T [n][k]: q,k bf16-hi; v,o fp16
__device__ unsigned short g_wl[4][DM*DM];    // q,k bf16-lo; v,o unused
__device__ float g_scr[GRID_SK][128*256];    // stream-K partials (QK: 256t*128; f512: 512t*32)
__device__ int   g_flag[GRID_SK+1];          // stream-K flags (self-resetting)

// ======================= helpers =============================================
__device__ __forceinline__ uint32_t smem_u32(const void* p) {
    uint32_t a;
    asm("{ .reg .u64 t; cvta.to.shared.u64 t, %1; cvt.u32.u64 %0, t; }" : "=r"(a) : "l"(p));
    return a;
}
__device__ __forceinline__ void cp_async16(uint32_t dst, const void* src) {
    asm volatile("cp.async.cg.shared.global [%0], [%1], 16;" :: "r"(dst), "l"(src));
}
#define CP_COMMIT() asm volatile("cp.async.commit_group;" ::: "memory")
#define CP_WAIT(N)  asm volatile("cp.async.wait_group %0;" :: "n"(N) : "memory")

#define LDSM4(r, addr) \
    asm volatile("ldmatrix.sync.aligned.m8n8.x4.shared.b16 {%0,%1,%2,%3}, [%4];" \
        : "=r"((r)[0]), "=r"((r)[1]), "=r"((r)[2]), "=r"((r)[3]) : "r"(addr))
#define LDSM4T(r, addr) \
    asm volatile("ldmatrix.sync.aligned.m8n8.x4.trans.shared.b16 {%0,%1,%2,%3}, [%4];" \
        : "=r"((r)[0]), "=r"((r)[1]), "=r"((r)[2]), "=r"((r)[3]) : "r"(addr))

#define MMA16816(c, a, b0, b1) \
    asm volatile("mma.sync.aligned.m16n8k16.row.col.f32.bf16.bf16.f32 " \
        "{%0,%1,%2,%3}, {%4,%5,%6,%7}, {%8,%9}, {%0,%1,%2,%3};" \
        : "+f"((c)[0]), "+f"((c)[1]), "+f"((c)[2]), "+f"((c)[3]) \
        : "r"((a)[0]), "r"((a)[1]), "r"((a)[2]), "r"((a)[3]), "r"(b0), "r"(b1))

#define MMAF16(c, a, b0, b1) \
    asm volatile("mma.sync.aligned.m16n8k16.row.col.f32.f16.f16.f32 " \
        "{%0,%1,%2,%3}, {%4,%5,%6,%7}, {%8,%9}, {%0,%1,%2,%3};" \
        : "+f"((c)[0]), "+f"((c)[1]), "+f"((c)[2]), "+f"((c)[3]) \
        : "r"((a)[0]), "r"((a)[1]), "r"((a)[2]), "r"((a)[3]), "r"(b0), "r"(b1))

__device__ __forceinline__ uint32_t pack_bf2(float x, float y) {
    __nv_bfloat162 t = __floats2bfloat162_rn(x, y);
    return *(uint32_t*)&t;
}
__device__ __forceinline__ float2 unpack_bf2(uint32_t u) {
    __nv_bfloat162 t = *(__nv_bfloat162*)&u;
    return __bfloat1622float2(t);
}
__device__ __forceinline__ uint32_t pack_h2(float x, float y) {
    __half2 t = __floats2half2_rn(x, y);
    return *(uint32_t*)&t;
}

// fast exp on the FMA pipe (args <= 0; clamp keeps scale exponent valid)
__device__ __forceinline__ float expp(float x) {
    x = fmaxf(x, -80.0f);
    float y = x * 1.4426950408889634f;
    float t = y + 12582912.0f;
    int   n = __float_as_int(t) - 0x4B400000;
    float f = y - (t - 12582912.0f);
    float g = f * 0.6931471805599453f;
    float p = fmaf(g, 0.008333333f, 0.041666668f);
    p = fmaf(p, g, 0.16666667f);
    p = fmaf(p, g, 0.5f);
    p = fmaf(p, g, 1.0f);
    p = fmaf(p, g, 1.0f);
    return p * __int_as_float((n + 127) << 23);
}

// ------ fp32 -> bf16 hi/lo split + fp16 single (elementwise) ----------------
__global__ void convert_split(const float* __restrict__ x,
                              unsigned short* __restrict__ oh,
                              unsigned short* __restrict__ ol,
                              unsigned short* __restrict__ of) {
    int i = blockIdx.x * blockDim.x + threadIdx.x;
    float4 v = ((const float4*)x)[i];
    uint32_t h01 = pack_bf2(v.x, v.y);
    uint32_t h23 = pack_bf2(v.z, v.w);
    float2 f01 = unpack_bf2(h01);
    float2 f23 = unpack_bf2(h23);
    uint32_t* ph = (uint32_t*)(oh + 4*(size_t)i);
    uint32_t* pl = (uint32_t*)(ol + 4*(size_t)i);
    uint32_t* pf = (uint32_t*)(of + 4*(size_t)i);
    ph[0] = h01; ph[1] = h23;
    pl[0] = pack_bf2(v.x - f01.x, v.y - f01.y);
    pl[1] = pack_bf2(v.z - f23.x, v.w - f23.y);
    pf[0] = pack_h2(v.x, v.y);
    pf[1] = pack_h2(v.z, v.w);
}

// ---- W converts (z=0..3) + bias table (z=4), one launch ---------------------
__global__ void convert_w_all(const float* __restrict__ W0, const float* __restrict__ W1,
                              const float* __restrict__ W2, const float* __restrict__ W3,
                              const float* __restrict__ rel_bias) {
    __shared__ float t[32][33];
    int z = blockIdx.z;
    int tx = threadIdx.x, ty = threadIdx.y;
    if (z == 4) {
        if (blockIdx.y != 0 || blockIdx.x >= NH) return;
        int h = blockIdx.x;
        int tid = ty * 32 + tx;
        for (int i = tid; i < 4096; i += 256) {
            int delta = i - 2048;
            int rb = (delta > 0) ? 16 : 0;
            int ar = delta < 0 ? -delta : delta;
            int bucket;
            if (ar < 8) {
                bucket = rb + ar;
            } else {
                int l = 8 + (int)(2.0f * log2f((float)ar * 0.125f));
                bucket = rb + (l > 15 ? 15 : l);
            }
            g_bias[h*4096 + i] = rel_bias[bucket*NH + h];
        }
        return;
    }
    const float* W = (z == 0) ? W0 : (z == 1) ? W1 : (z == 2) ? W2 : W3;
    unsigned short* oh = (unsigned short*)g_wh + (size_t)z * DM * DM;
    unsigned short* ol = (unsigned short*)g_wl + (size_t)z * DM * DM;
    int n0 = blockIdx.x * 32, k0 = blockIdx.y * 32;
    #pragma unroll
    for (int j = 0; j < 32; j += 8)
        t[ty + j][tx] = W[(size_t)(k0 + ty + j) * DM + n0 + tx];
    __syncthreads();
    #pragma unroll
    for (int j = 0; j < 32; j += 8) {
        float v = t[tx][ty + j];
        size_t o = (size_t)(n0 + ty + j) * DM + k0 + tx;
        if (z >= 2) {
            __half h = __float2half_rn(v);
            oh[o] = *(unsigned short*)&h;
        } else {
            __nv_bfloat16 h = __float2bfloat16_rn(v);
            oh[o] = *(unsigned short*)&h;
            __nv_bfloat16 l = __float2bfloat16_rn(v - __bfloat162float(h));
            ol[o] = *(unsigned short*)&l;
        }
    }
}

// ============== stream-K QK GEMM (bf16 3-pass, out bf16 hi/lo) ===============
#define PITCHB 80

__device__ __forceinline__ void tile_epi_qk(const float* acc, int m0, int n0,
                                            int wm, int wn, int lane,
                                            unsigned short* Ch, unsigned short* Cl)
{
    const int rbase = m0 + wm*64 + (lane >> 2);
    const int cbase = n0 + wn*64 + (lane & 3) * 2;
    #pragma unroll
    for (int mt = 0; mt < 4; mt++) {
        #pragma unroll
        for (int nt = 0; nt < 8; nt++) {
            const float* q = acc + (mt*8 + nt)*4;
            int row = rbase + mt*16;
            int col = cbase + nt*8;
            uint32_t h0 = pack_bf2(q[0], q[1]);
            float2 f0 = unpack_bf2(h0);
            *(uint32_t*)&Ch[(size_t)row * DM3 + col] = h0;
            *(uint32_t*)&Cl[(size_t)row * DM3 + col] = pack_bf2(q[0]-f0.x, q[1]-f0.y);
            uint32_t h1 = pack_bf2(q[2], q[3]);
            float2 f1 = unpack_bf2(h1);
            *(uint32_t*)&Ch[(size_t)(row+8) * DM3 + col] = h1;
            *(uint32_t*)&Cl[(size_t)(row+8) * DM3 + col] = pack_bf2(q[2]-f1.x, q[3]-f1.y);
        }
    }
}

#define QSAH 0
#define QSAL (128*PITCHB)
#define QSBH (2*128*PITCHB)
#define QSBL (QSBH + 256*PITCHB)
#define QSTG (QSBH + 2*256*PITCHB)

__global__ __launch_bounds__(256, 1) void gemm_qk(
    const unsigned short* __restrict__ Ah, const unsigned short* __restrict__ Al,
    const unsigned short* __restrict__ Bh, const unsigned short* __restrict__ Bl,
    unsigned short* __restrict__ Ch, unsigned short* __restrict__ Cl)
{
    extern __shared__ char smem[];
    const uint32_t sb0 = smem_u32(smem);
    const int tid  = threadIdx.x;
    const int lane = tid & 31;
    const int wm   = (tid >> 5) >> 2;
    const int wn   = (tid >> 5) & 3;
    const int cta  = blockIdx.x;
    const int G    = gridDim.x;

    const int total = 8192;           // 256 tiles (32m x 8n) x 32 chunks
    const int s = (int)(((long long)cta       * total) / G);
    const int e = (int)(((long long)(cta + 1) * total) / G);

    const uint32_t loff = (lane & 15) * PITCHB + ((lane >> 4) & 1) * 16;

    float acc[128];
    #pragma unroll
    for (int i = 0; i < 128; i++) acc[i] = 0.0f;

    #define LOAD_CHUNK(c, stg) do { \
        int t_  = (c) >> 5; \
        int m0_ = (t_ >> 3) * 128, n0_ = (t_ & 7) * 256, k0_ = ((c) & 31) * 32; \
        const uint32_t sb_ = sb0 + (stg) * QSTG; \
        _Pragma("unroll") \
        for (int tt = 0; tt < 2; tt++) { \
            int idx = tid + tt*256; int r = idx >> 2, cc = idx & 3; \
            cp_async16(sb_ + QSAH + r*PITCHB + cc*16, Ah + (size_t)(m0_+r)*DM + k0_ + cc*8); \
            cp_async16(sb_ + QSAL + r*PITCHB + cc*16, Al + (size_t)(m0_+r)*DM + k0_ + cc*8); \
        } \
        _Pragma("unroll") \
        for (int tt = 0; tt < 4; tt++) { \
            int idx = tid + tt*256; int r = idx >> 2, cc = idx & 3; \
            cp_async16(sb_ + QSBH + r*PITCHB + cc*16, Bh + (size_t)(n0_+r)*DM + k0_ + cc*8); \
            cp_async16(sb_ + QSBL + r*PITCHB + cc*16, Bl + (size_t)(n0_+r)*DM + k0_ + cc*8); \
        } \
        CP_COMMIT(); \
    } while (0)

    LOAD_CHUNK(s, 0);
    if (s + 1 < e) LOAD_CHUNK(s + 1, 1);
    int cur = 0;

    #pragma unroll 1
    for (int c = s; c < e; c++) {
        if (c + 1 < e) { CP_WAIT(1); } else { CP_WAIT(0); }
        __syncthreads();
        if (c + 2 < e) {
            int pf = cur - 1; if (pf < 0) pf = 2;
            LOAD_CHUNK(c + 2, pf);
        }

        const uint32_t sb = sb0 + cur * QSTG;
        cur = (cur == 2) ? 0 : cur + 1;

        #pragma unroll
        for (int kk = 0; kk < 2; kk++) {
            const uint32_t koff = kk * 32;
            uint32_t a[16], a2[16], bhf[16], blf[16];
            #pragma unroll
            for (int mt = 0; mt < 4; mt++)
                LDSM4(a + 4*mt,  sb + QSAH + (wm*64 + mt*16)*PITCHB + loff + koff);
            #pragma unroll
            for (int p = 0; p < 4; p++)
                LDSM4(bhf + 4*p, sb + QSBH + (wn*64 + p*16)*PITCHB + loff + koff);
            #pragma unroll
            for (int mt = 0; mt < 4; mt++)
                LDSM4(a2 + 4*mt, sb + QSAL + (wm*64 + mt*16)*PITCHB + loff + koff);
            #pragma unroll
            for (int p = 0; p < 4; p++)
                LDSM4(blf + 4*p, sb + QSBL + (wn*64 + p*16)*PITCHB + loff + koff);
            #pragma unroll
            for (int mt = 0; mt < 4; mt++)
                #pragma unroll
                for (int p = 0; p < 4; p++) {
                    MMA16816(acc + (mt*8 + 2*p)*4,   a + 4*mt, bhf[4*p+0], bhf[4*p+2]);
                    MMA16816(acc + (mt*8 + 2*p+1)*4, a + 4*mt, bhf[4*p+1], bhf[4*p+3]);
                }
            #pragma unroll
            for (int mt = 0; mt < 4; mt++)
                #pragma unroll
                for (int p = 0; p < 4; p++) {
                    MMA16816(acc + (mt*8 + 2*p)*4,   a2 + 4*mt, bhf[4*p+0], bhf[4*p+2]);
                    MMA16816(acc + (mt*8 + 2*p+1)*4, a2 + 4*mt, bhf[4*p+1], bhf[4*p+3]);
                }
            #pragma unroll
            for (int mt = 0; mt < 4; mt++)
                #pragma unroll
                for (int p = 0; p < 4; p++) {
                    MMA16816(acc + (mt*8 + 2*p)*4,   a + 4*mt, blf[4*p+0], blf[4*p+2]);
                    MMA16816(acc + (mt*8 + 2*p+1)*4, a + 4*mt, blf[4*p+1], blf[4*p+3]);
                }
        }

        const int t = c >> 5;
        if ((c & 31) == 31) {
            if (t * 32 >= s) {
                tile_epi_qk(acc, (t >> 3) * 128, (t & 7) * 256, wm, wn, lane, Ch, Cl);
            } else {
                float* slot = g_scr[cta] + (size_t)tid * 128;
                #pragma unroll
                for (int i = 0; i < 128; i += 4)
                    *(float4*)&slot[i] = *(float4*)&acc[i];
                __threadfence();
                __syncthreads();
                if (tid == 0) atomicExch(&g_flag[cta], 1);
            }
            #pragma unroll
            for (int i = 0; i < 128; i++) acc[i] = 0.0f;
        } else if (c == e - 1) {
            if (tid == 0) {
                while (atomicAdd(&g_flag[cta + 1], 0) == 0) { __nanosleep(64); }
                atomicExch(&g_flag[cta + 1], 0);
                __threadfence();
            }
            __syncthreads();
            const float* slot = g_scr[cta + 1] + (size_t)tid * 128;
            #pragma unroll
            for (int i = 0; i < 128; i += 4) {
                float4 v = __ldcv((const float4*)&slot[i]);
                acc[i+0] += v.x; acc[i+1] += v.y; acc[i+2] += v.z; acc[i+3] += v.w;
            }
            tile_epi_qk(acc, (t >> 3) * 128, (t & 7) * 256, wm, wn, lane, Ch, Cl);
        }
    }
    #undef LOAD_CHUNK
}

// ======== 512-thread stream-K fp16 1-pass GEMM (V and Wo), K-chunk 64 ========
// Tile 128x128, 16 warps (4m x 4n), warp tile 32x32, 4 warps/SMSP, 1 CTA/SM.
// 4096 chunks of K=64 (16 per tile), 27.7 chunks/CTA -> tiles span <=2 CTAs.
// Round-11 protocol: tail posts partial EARLY (its first tile boundary);
// head (range ends mid-tile) waits on flag[cta+1].
#define FPITCH 144               // 64 fp16 = 128B + 16B pad
#define FSAH 0
#define FSBH (128*FPITCH)
#define FSTG (2*128*FPITCH)      // 36864
#define FACC 32

template<int OUT>
__global__ __launch_bounds__(512, 1) void gemm_f512(
    const unsigned short* __restrict__ A, const unsigned short* __restrict__ B,
    unsigned short* __restrict__ Ch, float* __restrict__ Cf, int ldc)
{
    extern __shared__ char smem[];
    const uint32_t sb0 = smem_u32(smem);
    const int tid  = threadIdx.x;           // 0..511
    const int lane = tid & 31;
    const int wid  = tid >> 5;               // 0..15
    const int wm   = wid >> 2;               // 0..3
    const int wn   = wid & 3;                // 0..3
    const int cta  = blockIdx.x;
    const int G    = gridDim.x;

    const int total = 4096;                  // 256 tiles (32m x 8n) x 16 chunks
    const int s = (int)(((long long)cta       * total) / G);
    const int e = (int)(((long long)(cta + 1) * total) / G);

    const uint32_t loff = (lane & 15) * FPITCH + ((lane >> 4) & 1) * 16;

    float acc[FACC];
    #pragma unroll
    for (int i = 0; i < FACC; i++) acc[i] = 0.0f;

    #define LOAD_CHUNK(c, stg) do { \
        int t_ = (c) >> 4; \
        int m0_ = (t_ >> 3) * 128, n0_ = (t_ & 7) * 128, k0_ = ((c) & 15) * 64; \
        const uint32_t sb_ = sb0 + (stg) * FSTG; \
        _Pragma("unroll") \
        for (int tt = 0; tt < 2; tt++) { \
            int idx = tid + tt*512; int r = idx >> 3, cc = idx & 7; \
            cp_async16(sb_ + FSAH + r*FPITCH + cc*16, A + (size_t)(m0_+r)*DM + k0_ + cc*8); \
            cp_async16(sb_ + FSBH + r*FPITCH + cc*16, B + (size_t)(n0_+r)*DM + k0_ + cc*8); \
        } \
        CP_COMMIT(); \
    } while (0)

    LOAD_CHUNK(s, 0);
    if (s + 1 < e) LOAD_CHUNK(s + 1, 1);
    int cur = 0;

    #pragma unroll 1
    for (int c = s; c < e; c++) {
        if (c + 1 < e) { CP_WAIT(1); } else { CP_WAIT(0); }
        __syncthreads();
        if (c + 2 < e) {
            int pf = cur - 1; if (pf < 0) pf = 2;
            LOAD_CHUNK(c + 2, pf);
        }

        const uint32_t sb = sb0 + cur * FSTG;
        cur = (cur == 2) ? 0 : cur + 1;

        #pragma unroll
        for (int kk = 0; kk < 4; kk++) {
            const uint32_t koff = kk * 32;
            uint32_t a[8], b[8];
            LDSM4(a,     sb + FSAH + (wm*32)*FPITCH      + loff + koff);
            LDSM4(a + 4, sb + FSAH + (wm*32 + 16)*FPITCH + loff + koff);
            LDSM4(b,     sb + FSBH + (wn*32)*FPITCH      + loff + koff);
            LDSM4(b + 4, sb + FSBH + (wn*32 + 16)*FPITCH + loff + koff);
            #pragma unroll
            for (int mt = 0; mt < 2; mt++)
                #pragma unroll
                for (int p = 0; p < 2; p++) {
                    MMAF16(acc + (mt*4 + 2*p)*4,   a + 4*mt, b[4*p+0], b[4*p+2]);
                    MMAF16(acc + (mt*4 + 2*p+1)*4, a + 4*mt, b[4*p+1], b[4*p+3]);
                }
        }

        const int t = c >> 4;
        if ((c & 15) == 15) {
            if (t * 16 >= s) {
                // full tile owned: write out
                const int rbase = (t >> 3) * 128 + wm*32 + (lane >> 2);
                const int cbase = (t & 7) * 128 + wn*32 + (lane & 3) * 2;
                #pragma unroll
                for (int mt = 0; mt < 2; mt++)
                    #pragma unroll
                    for (int nt = 0; nt < 4; nt++) {
                        const float* q = acc + (mt*4 + nt)*4;
                        int row = rbase + mt*16, col = cbase + nt*8;
                        if (OUT == 0) {
                            *(uint32_t*)&Ch[(size_t)row * ldc + col]     = pack_h2(q[0], q[1]);
                            *(uint32_t*)&Ch[(size_t)(row+8) * ldc + col] = pack_h2(q[2], q[3]);
                        } else {
                            float2 v0; v0.x = q[0]; v0.y = q[1];
                            float2 v1; v1.x = q[2]; v1.y = q[3];
                            *(float2*)&Cf[(size_t)row * ldc + col]       = v0;
                            *(float2*)&Cf[(size_t)(row + 8) * ldc + col] = v1;
                        }
                    }
            } else {
                // tail of split tile: post partial EARLY (first tile of range)
                float* slot = g_scr[cta] + (size_t)tid * FACC;
                #pragma unroll
                for (int i = 0; i < FACC; i += 4)
                    *(float4*)&slot[i] = *(float4*)&acc[i];
                __threadfence();
                __syncthreads();
                if (tid == 0) atomicExch(&g_flag[cta], 1);
            }
            #pragma unroll
            for (int i = 0; i < FACC; i++) acc[i] = 0.0f;
        } else if (c == e - 1) {
            // head of split tile: wait for cta+1's early post, add, write
            if (tid == 0) {
                while (atomicAdd(&g_flag[cta + 1], 0) == 0) { __nanosleep(64); }
                atomicExch(&g_flag[cta + 1], 0);
                __threadfence();
            }
            __syncthreads();
            const float* slot = g_scr[cta + 1] + (size_t)tid * FACC;
            #pragma unroll
            for (int i = 0; i < FACC; i += 4) {
                float4 v = __ldcv((const float4*)&slot[i]);
                acc[i+0] += v.x; acc[i+1] += v.y; acc[i+2] += v.z; acc[i+3] += v.w;
            }
            const int rbase = (t >> 3) * 128 + wm*32 + (lane >> 2);
            const int cbase = (t & 7) * 128 + wn*32 + (lane & 3) * 2;
            #pragma unroll
            for (int mt = 0; mt < 2; mt++)
                #pragma unroll
                for (int nt = 0; nt < 4; nt++) {
                    const float* q = acc + (mt*4 + nt)*4;
                    int row = rbase + mt*16, col = cbase + nt*8;
                    if (OUT == 0) {
                        *(uint32_t*)&Ch[(size_t)row * ldc + col]     = pack_h2(q[0], q[1]);
                        *(uint32_t*)&Ch[(size_t)(row+8) * ldc + col] = pack_h2(q[2], q[3]);
                    } else {
                        float2 v0; v0.x = q[0]; v0.y = q[1];
                        float2 v1; v1.x = q[2]; v1.y = q[3];
                        *(float2*)&Cf[(size_t)row * ldc + col]       = v0;
                        *(float2*)&Cf[(size_t)(row + 8) * ldc + col] = v1;
                    }
                }
        }
    }
    #undef LOAD_CHUNK
}

// ============== MMA flash attention (BQ=64, 4 warps, 3 CTAs/SM) =============
#define BQ 64
#define BK 64
#define PB 144
#define SQ_H 0
#define SQ_L 9216
#define STG0 18432
#define STGSZ 27648
#define ATTN_SMEM (STG0 + 2*STGSZ)   // 73728

__global__ __launch_bounds__(128, 3) void attn_mma() {
    extern __shared__ char smc[];
    const uint32_t sb = smem_u32(smc);
    const int tid  = threadIdx.x;
    const int w    = tid >> 5;
    const int lane = tid & 31;
    const int bh = blockIdx.y, h = bh & 15, b = bh >> 4;
    const int q0 = blockIdx.x * BQ;
    const int rowbase = b * SEQ;

    const unsigned short* gxh = g_xh;
    const unsigned short* gxl = g_xl;

    #pragma unroll
    for (int t = 0; t < 8; t++) {
        int idx = tid + t*128;
        int arr = idx >> 9;
        int i2  = idx & 511;
        int r   = i2 >> 3, cc = i2 & 7;
        const unsigned short* src = (arr ? gxl : gxh)
            + (size_t)(rowbase + q0 + r) * DM3 + h*DH + cc*8;
        cp_async16(sb + (arr ? SQ_L : SQ_H) + r*PB + cc*16, src);
    }

    #define LOADKV(j) do { \
        const uint32_t st_ = sb + STG0 + ((j) & 1) * STGSZ; \
        const int kk0 = (j) * BK; \
        _Pragma("unroll") \
        for (int t = 0; t < 12; t++) { \
            int idx = tid + t*128; \
            int arr = idx >> 9; int i2 = idx & 511; \
            int r = i2 >> 3, cc = i2 & 7; \
            const unsigned short* srcp = (arr == 0) ? (gxh + 1024) \
                                       : (arr == 1) ? (gxl + 1024) : (gxh + 2048); \
            srcp += (size_t)(rowbase + kk0 + r) * DM3 + h*DH + cc*8; \
            cp_async16(st_ + arr*9216 + r*PB + cc*16, srcp); \
        } \
    } while (0)

    LOADKV(0);
    CP_COMMIT();

    const uint32_t loff = (lane & 15) * PB + (lane >> 4) * 16;
    uint32_t qfh[4][4], qfl[4][4];

    float o[8][4];
    #pragma unroll
    for (int dt = 0; dt < 8; dt++)
        #pragma unroll
        for (int q = 0; q < 4; q++) o[dt][q] = 0.0f;
    float m0r = -1e30f, m1r = -1e30f, l0r = 0.0f, l1r = 0.0f;

    const float* bt = g_bias + h * 4096;
    const int row0 = lane >> 2;
    const int col2 = (lane & 3) * 2;

    #pragma unroll 1
    for (int i = 0; i < SEQ/BK; i++) {
        if (i + 1 < SEQ/BK) LOADKV(i + 1);
        CP_COMMIT();
        CP_WAIT(1);
        __syncthreads();

        if (i == 0) {
            #pragma unroll
            for (int ks = 0; ks < 4; ks++) {
                LDSM4(qfh[ks], sb + SQ_H + w*16*PB + loff + ks*32);
                LDSM4(qfl[ks], sb + SQ_L + w*16*PB + loff + ks*32);
            }
        }

        const uint32_t st = sb + STG0 + (i & 1) * STGSZ;

        float s[8][4];
        #pragma unroll
        for (int nt = 0; nt < 8; nt++)
            #pragma unroll
            for (int q = 0; q < 4; q++) s[nt][q] = 0.0f;

        #pragma unroll
        for (int ks = 0; ks < 4; ks++) {
            #pragma unroll
            for (int np = 0; np < 4; np++) {
                uint32_t bh4[4], bl4[4];
                LDSM4(bh4, st + (np*16)*PB + loff + ks*32);
                LDSM4(bl4, st + 9216 + (np*16)*PB + loff + ks*32);
                MMA16816(s[2*np],   qfh[ks], bh4[0], bh4[2]);
                MMA16816(s[2*np+1], qfh[ks], bh4[1], bh4[3]);
                MMA16816(s[2*np],   qfl[ks], bh4[0], bh4[2]);
                MMA16816(s[2*np+1], qfl[ks], bh4[1], bh4[3]);
                MMA16816(s[2*np],   qfh[ks], bl4[0], bl4[2]);
                MMA16816(s[2*np+1], qfh[ks], bl4[1], bl4[3]);
            }
        }

        const float* bp0 = bt + 2048 + i*BK + col2 - (q0 + w*16 + row0);
        #pragma unroll
        for (int nt = 0; nt < 8; nt++) {
            s[nt][0] += __ldg(bp0 + nt*8);
            s[nt][1] += __ldg(bp0 + nt*8 + 1);
            s[nt][2] += __ldg(bp0 + nt*8 - 8);
            s[nt][3] += __ldg(bp0 + nt*8 - 7);
        }

        float t0 = -1e30f, t1 = -1e30f;
        #pragma unroll
        for (int nt = 0; nt < 8; nt++) {
            t0 = fmaxf(t0, fmaxf(s[nt][0], s[nt][1]));
            t1 = fmaxf(t1, fmaxf(s[nt][2], s[nt][3]));
        }
        t0 = fmaxf(t0, __shfl_xor_sync(0xffffffffu, t0, 1));
        t0 = fmaxf(t0, __shfl_xor_sync(0xffffffffu, t0, 2));
        t1 = fmaxf(t1, __shfl_xor_sync(0xffffffffu, t1, 1));
        t1 = fmaxf(t1, __shfl_xor_sync(0xffffffffu, t1, 2));
        float mn0 = fmaxf(m0r, t0), mn1 = fmaxf(m1r, t1);
        float a0 = expp(m0r - mn0), a1 = expp(m1r - mn1);
        m0r = mn0; m1r = mn1;

        float ps0 = 0.0f, ps1 = 0.0f;
        #pragma unroll
        for (int nt = 0; nt < 8; nt++) {
            s[nt][0] = expp(s[nt][0] - mn0);
            s[nt][1] = expp(s[nt][1] - mn0);
            s[nt][2] = expp(s[nt][2] - mn1);
            s[nt][3] = expp(s[nt][3] - mn1);
            ps0 += s[nt][0] + s[nt][1];
            ps1 += s[nt][2] + s[nt][3];
        }
        ps0 += __shfl_xor_sync(0xffffffffu, ps0, 1);
        ps0 += __shfl_xor_sync(0xffffffffu, ps0, 2);
        ps1 += __shfl_xor_sync(0xffffffffu, ps1, 1);
        ps1 += __shfl_xor_sync(0xffffffffu, ps1, 2);
        l0r = l0r * a0 + ps0;
        l1r = l1r * a1 + ps1;
        #pragma unroll
        for (int dt = 0; dt < 8; dt++) {
            o[dt][0] *= a0; o[dt][1] *= a0;
            o[dt][2] *= a1; o[dt][3] *= a1;
        }

        #pragma unroll
        for (int ks = 0; ks < 4; ks++) {
            uint32_t ph4[4];
            #pragma unroll
            for (int q = 0; q < 4; q++) {
                int nt = 2*ks + (q >> 1);
                ph4[q] = pack_h2(s[nt][(q & 1) * 2], s[nt][(q & 1) * 2 + 1]);
            }
            #pragma unroll
            for (int dp = 0; dp < 4; dp++) {
                uint32_t vh4[4];
                LDSM4T(vh4, st + 18432 + (ks*16 + (lane & 15))*PB + dp*32 + (lane >> 4)*16);
                MMAF16(o[2*dp],   ph4, vh4[0], vh4[1]);
                MMAF16(o[2*dp+1], ph4, vh4[2], vh4[3]);
            }
        }
        __syncthreads();
    }
    #undef LOADKV

    float inv0 = 1.0f / l0r, inv1 = 1.0f / l1r;
    unsigned short* oh = g_ah;
    const size_t gr0 = (size_t)(rowbase + q0 + w*16 + row0) * DM + h*DH;
    const size_t gr1 = gr0 + 8 * DM;
    #pragma unroll
    for (int dt = 0; dt < 8; dt++) {
        int col = dt*8 + col2;
        *(uint32_t*)&oh[gr0 + col] = pack_h2(o[dt][0]*inv0, o[dt][1]*inv0);
        *(uint32_t*)&oh[gr1 + col] = pack_h2(o[dt][2]*inv1, o[dt][3]*inv1);
    }
}

// ---------------- launch -----------------------------------------------------
extern "C" void kernel_launch(void* const* d_in, const int* in_sizes, int n_in,
                              void* d_out, int out_size) {
    const float* hidden = (const float*)d_in[0];
    const float* Wq     = (const float*)d_in[1];
    const float* Wk     = (const float*)d_in[2];
    const float* Wv     = (const float*)d_in[3];
    const float* Wo     = (const float*)d_in[4];
    const float* relb   = (const float*)d_in[5];
    float* out = (float*)d_out;

    void *phh, *phl, *phf, *pxh, *pxl, *pah, *pwh, *pwl;
    cudaGetSymbolAddress(&phh, g_hh);
    cudaGetSymbolAddress(&phl, g_hl);
    cudaGetSymbolAddress(&phf, g_hf);
    cudaGetSymbolAddress(&pxh, g_xh);
    cudaGetSymbolAddress(&pxl, g_xl);
    cudaGetSymbolAddress(&pah, g_ah);
    cudaGetSymbolAddress(&pwh, g_wh);
    cudaGetSymbolAddress(&pwl, g_wl);

    unsigned short* hh = (unsigned short*)phh;
    unsigned short* hl = (unsigned short*)phl;
    unsigned short* hf = (unsigned short*)phf;
    unsigned short* xh = (unsigned short*)pxh;
    unsigned short* xl = (unsigned short*)pxl;
    unsigned short* ah = (unsigned short*)pah;
    unsigned short* wh = (unsigned short*)pwh;
    unsigned short* wl = (unsigned short*)pwl;

    int dev = 0, sms = GRID_SK;
    cudaGetDevice(&dev);
    cudaDeviceGetAttribute(&sms, cudaDevAttrMultiProcessorCount, dev);
    int grid1 = (sms < GRID_SK) ? sms : GRID_SK;

    convert_split<<<(MROWS*DM/4)/256, 256>>>(hidden, hh, hl, hf);
    convert_w_all<<<dim3(DM/32, DM/32, 5), dim3(32, 8)>>>(Wq, Wk, Wv, Wo, relb);

    const int QK_SMEM = 3 * QSTG;    // 184320
    const int F_SMEM  = 3 * FSTG;    // 110592
    cudaFuncSetAttribute(gemm_qk, cudaFuncAttributeMaxDynamicSharedMemorySize, QK_SMEM);
    cudaFuncSetAttribute(gemm_f512<0>, cudaFuncAttributeMaxDynamicSharedMemorySize, F_SMEM);
    cudaFuncSetAttribute(gemm_f512<1>, cudaFuncAttributeMaxDynamicSharedMemorySize, F_SMEM);

    // QK projections: N=2048, bf16 3-pass, out bf16 hi/lo into xh/xl cols 0..2047
    gemm_qk<<<grid1, 256, QK_SMEM>>>(hh, hl, wh, wl, xh, xl);

    // V projection: fp16 1-pass, 512 threads, K-chunk 64, out fp16 cols 2048..3071
    gemm_f512<0><<<grid1, 512, F_SMEM>>>(hf, wh + 2*(size_t)DM*DM,
                                         xh + 2048, nullptr, DM3);

    cudaFuncSetAttribute(attn_mma, cudaFuncAttributeMaxDynamicSharedMemorySize, ATTN_SMEM);
    attn_mma<<<dim3(SEQ/BQ, BATCH*NH), 128, ATTN_SMEM>>>();

    // Wo: fp16 1-pass, 512 threads, K-chunk 64, fp32 out
    gemm_f512<1><<<grid1, 512, F_SMEM>>>(ah, wh + 3*(size_t)DM*DM,
                                         nullptr, out, DM);
}

// round 17
// speedup vs baseline: 2.1801x; 1.0034x over previous
#include <cuda_runtime.h>
#include <cuda_bf16.h>
#include <cuda_fp16.h>
#include <math.h>
#include <stdint.h>

#define SEQ   2048
#define NH    16
#define DH    64
#define DM    1024
#define DM3   3072
#define BATCH 2
#define MROWS (BATCH*SEQ)   // 4096
#define GRID_SK 148

// ---------------- scratch (device globals; no allocations allowed) ----------
__device__ float g_bias[NH*4096];            // per-head bias vs (j-i)+2048
__device__ unsigned short g_hh[MROWS*DM];    // hidden bf16 hi
__device__ unsigned short g_hl[MROWS*DM];    // hidden bf16 lo
__device__ unsigned short g_hf[MROWS*DM];    // hidden fp16 single (V path)
__device__ unsigned short g_xh[MROWS*DM3];   // Q,K bf16-hi | V fp16   [row][3072]
__device__ unsigned short g_xl[MROWS*DM3];   // Q,K bf16-lo | (unused)
__device__ unsigned short g_ah[MROWS*DM];    // attn out fp16 single
__device__ unsigned short g_wh[4][DM*DM];    // W^T [n][k]: q,k bf16-hi; v,o fp16
__device__ unsigned short g_wl[4][DM*DM];    // q,k bf16-lo; v,o unused
__device__ float g_scr[GRID_SK][128*256];    // stream-K partials (QK: 256t*128; f512: 512t*32)
__device__ int   g_flag[GRID_SK+1];          // stream-K flags (self-resetting)

// ======================= helpers =============================================
__device__ __forceinline__ uint32_t smem_u32(const void* p) {
    uint32_t a;
    asm("{ .reg .u64 t; cvta.to.shared.u64 t, %1; cvt.u32.u64 %0, t; }" : "=r"(a) : "l"(p));
    return a;
}
__device__ __forceinline__ void cp_async16(uint32_t dst, const void* src) {
    asm volatile("cp.async.cg.shared.global [%0], [%1], 16;" :: "r"(dst), "l"(src));
}
#define CP_COMMIT() asm volatile("cp.async.commit_group;" ::: "memory")
#define CP_WAIT(N)  asm volatile("cp.async.wait_group %0;" :: "n"(N) : "memory")

#define LDSM4(r, addr) \
    asm volatile("ldmatrix.sync.aligned.m8n8.x4.shared.b16 {%0,%1,%2,%3}, [%4];" \
        : "=r"((r)[0]), "=r"((r)[1]), "=r"((r)[2]), "=r"((r)[3]) : "r"(addr))
#define LDSM4T(r, addr) \
    asm volatile("ldmatrix.sync.aligned.m8n8.x4.trans.shared.b16 {%0,%1,%2,%3}, [%4];" \
        : "=r"((r)[0]), "=r"((r)[1]), "=r"((r)[2]), "=r"((r)[3]) : "r"(addr))

#define MMA16816(c, a, b0, b1) \
    asm volatile("mma.sync.aligned.m16n8k16.row.col.f32.bf16.bf16.f32 " \
        "{%0,%1,%2,%3}, {%4,%5,%6,%7}, {%8,%9}, {%0,%1,%2,%3};" \
        : "+f"((c)[0]), "+f"((c)[1]), "+f"((c)[2]), "+f"((c)[3]) \
        : "r"((a)[0]), "r"((a)[1]), "r"((a)[2]), "r"((a)[3]), "r"(b0), "r"(b1))

#define MMAF16(c, a, b0, b1) \
    asm volatile("mma.sync.aligned.m16n8k16.row.col.f32.f16.f16.f32 " \
        "{%0,%1,%2,%3}, {%4,%5,%6,%7}, {%8,%9}, {%0,%1,%2,%3};" \
        : "+f"((c)[0]), "+f"((c)[1]), "+f"((c)[2]), "+f"((c)[3]) \
        : "r"((a)[0]), "r"((a)[1]), "r"((a)[2]), "r"((a)[3]), "r"(b0), "r"(b1))

__device__ __forceinline__ uint32_t pack_bf2(float x, float y) {
    __nv_bfloat162 t = __floats2bfloat162_rn(x, y);
    return *(uint32_t*)&t;
}
__device__ __forceinline__ float2 unpack_bf2(uint32_t u) {
    __nv_bfloat162 t = *(__nv_bfloat162*)&u;
    return __bfloat1622float2(t);
}
__device__ __forceinline__ uint32_t pack_h2(float x, float y) {
    __half2 t = __floats2half2_rn(x, y);
    return *(uint32_t*)&t;
}

// fast exp on the FMA pipe (args <= 0; clamp keeps scale exponent valid)
__device__ __forceinline__ float expp(float x) {
    x = fmaxf(x, -80.0f);
    float y = x * 1.4426950408889634f;
    float t = y + 12582912.0f;
    int   n = __float_as_int(t) - 0x4B400000;
    float f = y - (t - 12582912.0f);
    float g = f * 0.6931471805599453f;
    float p = fmaf(g, 0.008333333f, 0.041666668f);
    p = fmaf(p, g, 0.16666667f);
    p = fmaf(p, g, 0.5f);
    p = fmaf(p, g, 1.0f);
    p = fmaf(p, g, 1.0f);
    return p * __int_as_float((n + 127) << 23);
}

// ------ fp32 -> bf16 hi/lo split + fp16 single (elementwise) ----------------
__global__ void convert_split(const float* __restrict__ x,
                              unsigned short* __restrict__ oh,
                              unsigned short* __restrict__ ol,
                              unsigned short* __restrict__ of) {
    int i = blockIdx.x * blockDim.x + threadIdx.x;
    float4 v = ((const float4*)x)[i];
    uint32_t h01 = pack_bf2(v.x, v.y);
    uint32_t h23 = pack_bf2(v.z, v.w);
    float2 f01 = unpack_bf2(h01);
    float2 f23 = unpack_bf2(h23);
    uint32_t* ph = (uint32_t*)(oh + 4*(size_t)i);
    uint32_t* pl = (uint32_t*)(ol + 4*(size_t)i);
    uint32_t* pf = (uint32_t*)(of + 4*(size_t)i);
    ph[0] = h01; ph[1] = h23;
    pl[0] = pack_bf2(v.x - f01.x, v.y - f01.y);
    pl[1] = pack_bf2(v.z - f23.x, v.w - f23.y);
    pf[0] = pack_h2(v.x, v.y);
    pf[1] = pack_h2(v.z, v.w);
}

// ---- W converts (z=0..3) + bias table (z=4), one launch ---------------------
__global__ void convert_w_all(const float* __restrict__ W0, const float* __restrict__ W1,
                              const float* __restrict__ W2, const float* __restrict__ W3,
                              const float* __restrict__ rel_bias) {
    __shared__ float t[32][33];
    int z = blockIdx.z;
    int tx = threadIdx.x, ty = threadIdx.y;
    if (z == 4) {
        if (blockIdx.y != 0 || blockIdx.x >= NH) return;
        int h = blockIdx.x;
        int tid = ty * 32 + tx;
        for (int i = tid; i < 4096; i += 256) {
            int delta = i - 2048;
            int rb = (delta > 0) ? 16 : 0;
            int ar = delta < 0 ? -delta : delta;
            int bucket;
            if (ar < 8) {
                bucket = rb + ar;
            } else {
                int l = 8 + (int)(2.0f * log2f((float)ar * 0.125f));
                bucket = rb + (l > 15 ? 15 : l);
            }
            g_bias[h*4096 + i] = rel_bias[bucket*NH + h];
        }
        return;
    }
    const float* W = (z == 0) ? W0 : (z == 1) ? W1 : (z == 2) ? W2 : W3;
    unsigned short* oh = (unsigned short*)g_wh + (size_t)z * DM * DM;
    unsigned short* ol = (unsigned short*)g_wl + (size_t)z * DM * DM;
    int n0 = blockIdx.x * 32, k0 = blockIdx.y * 32;
    #pragma unroll
    for (int j = 0; j < 32; j += 8)
        t[ty + j][tx] = W[(size_t)(k0 + ty + j) * DM + n0 + tx];
    __syncthreads();
    #pragma unroll
    for (int j = 0; j < 32; j += 8) {
        float v = t[tx][ty + j];
        size_t o = (size_t)(n0 + ty + j) * DM + k0 + tx;
        if (z >= 2) {
            __half h = __float2half_rn(v);
            oh[o] = *(unsigned short*)&h;
        } else {
            __nv_bfloat16 h = __float2bfloat16_rn(v);
            oh[o] = *(unsigned short*)&h;
            __nv_bfloat16 l = __float2bfloat16_rn(v - __bfloat162float(h));
            ol[o] = *(unsigned short*)&l;
        }
    }
}

// ============== stream-K QK GEMM (bf16 3-pass, out bf16 hi/lo) ===============
#define PITCHB 80

__device__ __forceinline__ void tile_epi_qk(const float* acc, int m0, int n0,
                                            int wm, int wn, int lane,
                                            unsigned short* Ch, unsigned short* Cl)
{
    const int rbase = m0 + wm*64 + (lane >> 2);
    const int cbase = n0 + wn*64 + (lane & 3) * 2;
    #pragma unroll
    for (int mt = 0; mt < 4; mt++) {
        #pragma unroll
        for (int nt = 0; nt < 8; nt++) {
            const float* q = acc + (mt*8 + nt)*4;
            int row = rbase + mt*16;
            int col = cbase + nt*8;
            uint32_t h0 = pack_bf2(q[0], q[1]);
            float2 f0 = unpack_bf2(h0);
            *(uint32_t*)&Ch[(size_t)row * DM3 + col] = h0;
            *(uint32_t*)&Cl[(size_t)row * DM3 + col] = pack_bf2(q[0]-f0.x, q[1]-f0.y);
            uint32_t h1 = pack_bf2(q[2], q[3]);
            float2 f1 = unpack_bf2(h1);
            *(uint32_t*)&Ch[(size_t)(row+8) * DM3 + col] = h1;
            *(uint32_t*)&Cl[(size_t)(row+8) * DM3 + col] = pack_bf2(q[2]-f1.x, q[3]-f1.y);
        }
    }
}

#define QSAH 0
#define QSAL (128*PITCHB)
#define QSBH (2*128*PITCHB)
#define QSBL (QSBH + 256*PITCHB)
#define QSTG (QSBH + 2*256*PITCHB)

__global__ __launch_bounds__(256, 1) void gemm_qk(
    const unsigned short* __restrict__ Ah, const unsigned short* __restrict__ Al,
    const unsigned short* __restrict__ Bh, const unsigned short* __restrict__ Bl,
    unsigned short* __restrict__ Ch, unsigned short* __restrict__ Cl)
{
    extern __shared__ char smem[];
    const uint32_t sb0 = smem_u32(smem);
    const int tid  = threadIdx.x;
    const int lane = tid & 31;
    const int wm   = (tid >> 5) >> 2;
    const int wn   = (tid >> 5) & 3;
    const int cta  = blockIdx.x;
    const int G    = gridDim.x;

    const int total = 8192;           // 256 tiles (32m x 8n) x 32 chunks
    const int s = (int)(((long long)cta       * total) / G);
    const int e = (int)(((long long)(cta + 1) * total) / G);

    const uint32_t loff = (lane & 15) * PITCHB + ((lane >> 4) & 1) * 16;

    float acc[128];
    #pragma unroll
    for (int i = 0; i < 128; i++) acc[i] = 0.0f;

    #define LOAD_CHUNK(c, stg) do { \
        int t_  = (c) >> 5; \
        int m0_ = (t_ >> 3) * 128, n0_ = (t_ & 7) * 256, k0_ = ((c) & 31) * 32; \
        const uint32_t sb_ = sb0 + (stg) * QSTG; \
        _Pragma("unroll") \
        for (int tt = 0; tt < 2; tt++) { \
            int idx = tid + tt*256; int r = idx >> 2, cc = idx & 3; \
            cp_async16(sb_ + QSAH + r*PITCHB + cc*16, Ah + (size_t)(m0_+r)*DM + k0_ + cc*8); \
            cp_async16(sb_ + QSAL + r*PITCHB + cc*16, Al + (size_t)(m0_+r)*DM + k0_ + cc*8); \
        } \
        _Pragma("unroll") \
        for (int tt = 0; tt < 4; tt++) { \
            int idx = tid + tt*256; int r = idx >> 2, cc = idx & 3; \
            cp_async16(sb_ + QSBH + r*PITCHB + cc*16, Bh + (size_t)(n0_+r)*DM + k0_ + cc*8); \
            cp_async16(sb_ + QSBL + r*PITCHB + cc*16, Bl + (size_t)(n0_+r)*DM + k0_ + cc*8); \
        } \
        CP_COMMIT(); \
    } while (0)

    LOAD_CHUNK(s, 0);
    if (s + 1 < e) LOAD_CHUNK(s + 1, 1);
    int cur = 0;

    #pragma unroll 1
    for (int c = s; c < e; c++) {
        if (c + 1 < e) { CP_WAIT(1); } else { CP_WAIT(0); }
        __syncthreads();
        if (c + 2 < e) {
            int pf = cur - 1; if (pf < 0) pf = 2;
            LOAD_CHUNK(c + 2, pf);
        }

        const uint32_t sb = sb0 + cur * QSTG;
        cur = (cur == 2) ? 0 : cur + 1;

        #pragma unroll
        for (int kk = 0; kk < 2; kk++) {
            const uint32_t koff = kk * 32;
            uint32_t a[16], a2[16], bhf[16], blf[16];
            #pragma unroll
            for (int mt = 0; mt < 4; mt++)
                LDSM4(a + 4*mt,  sb + QSAH + (wm*64 + mt*16)*PITCHB + loff + koff);
            #pragma unroll
            for (int p = 0; p < 4; p++)
                LDSM4(bhf + 4*p, sb + QSBH + (wn*64 + p*16)*PITCHB + loff + koff);
            #pragma unroll
            for (int mt = 0; mt < 4; mt++)
                LDSM4(a2 + 4*mt, sb + QSAL + (wm*64 + mt*16)*PITCHB + loff + koff);
            #pragma unroll
            for (int p = 0; p < 4; p++)
                LDSM4(blf + 4*p, sb + QSBL + (wn*64 + p*16)*PITCHB + loff + koff);
            #pragma unroll
            for (int mt = 0; mt < 4; mt++)
                #pragma unroll
                for (int p = 0; p < 4; p++) {
                    MMA16816(acc + (mt*8 + 2*p)*4,   a + 4*mt, bhf[4*p+0], bhf[4*p+2]);
                    MMA16816(acc + (mt*8 + 2*p+1)*4, a + 4*mt, bhf[4*p+1], bhf[4*p+3]);
                }
            #pragma unroll
            for (int mt = 0; mt < 4; mt++)
                #pragma unroll
                for (int p = 0; p < 4; p++) {
                    MMA16816(acc + (mt*8 + 2*p)*4,   a2 + 4*mt, bhf[4*p+0], bhf[4*p+2]);
                    MMA16816(acc + (mt*8 + 2*p+1)*4, a2 + 4*mt, bhf[4*p+1], bhf[4*p+3]);
                }
            #pragma unroll
            for (int mt = 0; mt < 4; mt++)
                #pragma unroll
                for (int p = 0; p < 4; p++) {
                    MMA16816(acc + (mt*8 + 2*p)*4,   a + 4*mt, blf[4*p+0], blf[4*p+2]);
                    MMA16816(acc + (mt*8 + 2*p+1)*4, a + 4*mt, blf[4*p+1], blf[4*p+3]);
                }
        }

        const int t = c >> 5;
        if ((c & 31) == 31) {
            if (t * 32 >= s) {
                tile_epi_qk(acc, (t >> 3) * 128, (t & 7) * 256, wm, wn, lane, Ch, Cl);
            } else {
                float* slot = g_scr[cta] + (size_t)tid * 128;
                #pragma unroll
                for (int i = 0; i < 128; i += 4)
                    *(float4*)&slot[i] = *(float4*)&acc[i];
                __threadfence();
                __syncthreads();
                if (tid == 0) atomicExch(&g_flag[cta], 1);
            }
            #pragma unroll
            for (int i = 0; i < 128; i++) acc[i] = 0.0f;
        } else if (c == e - 1) {
            if (tid == 0) {
                while (atomicAdd(&g_flag[cta + 1], 0) == 0) { __nanosleep(64); }
                atomicExch(&g_flag[cta + 1], 0);
                __threadfence();
            }
            __syncthreads();
            const float* slot = g_scr[cta + 1] + (size_t)tid * 128;
            #pragma unroll
            for (int i = 0; i < 128; i += 4) {
                float4 v = __ldcv((const float4*)&slot[i]);
                acc[i+0] += v.x; acc[i+1] += v.y; acc[i+2] += v.z; acc[i+3] += v.w;
            }
            tile_epi_qk(acc, (t >> 3) * 128, (t & 7) * 256, wm, wn, lane, Ch, Cl);
        }
    }
    #undef LOAD_CHUNK
}

// ======== 512-thread stream-K fp16 1-pass GEMM (V and Wo), K-chunk 64 ========
// Tile 128x128, 16 warps (4m x 4n), warp tile 32x32, 4 warps/SMSP, 1 CTA/SM.
// kk loop register double-buffered: LDSMs for kk+1 issue before kk's MMAs.
#define FPITCH 144               // 64 fp16 = 128B + 16B pad
#define FSAH 0
#define FSBH (128*FPITCH)
#define FSTG (2*128*FPITCH)      // 36864
#define FACC 32

template<int OUT>
__global__ __launch_bounds__(512, 1) void gemm_f512(
    const unsigned short* __restrict__ A, const unsigned short* __restrict__ B,
    unsigned short* __restrict__ Ch, float* __restrict__ Cf, int ldc)
{
    extern __shared__ char smem[];
    const uint32_t sb0 = smem_u32(smem);
    const int tid  = threadIdx.x;           // 0..511
    const int lane = tid & 31;
    const int wid  = tid >> 5;               // 0..15
    const int wm   = wid >> 2;               // 0..3
    const int wn   = wid & 3;                // 0..3
    const int cta  = blockIdx.x;
    const int G    = gridDim.x;

    const int total = 4096;                  // 256 tiles (32m x 8n) x 16 chunks
    const int s = (int)(((long long)cta       * total) / G);
    const int e = (int)(((long long)(cta + 1) * total) / G);

    const uint32_t loff = (lane & 15) * FPITCH + ((lane >> 4) & 1) * 16;
    const uint32_t abase = FSAH + (wm*32)*FPITCH + loff;
    const uint32_t bbase = FSBH + (wn*32)*FPITCH + loff;

    float acc[FACC];
    #pragma unroll
    for (int i = 0; i < FACC; i++) acc[i] = 0.0f;

    #define LOAD_CHUNK(c, stg) do { \
        int t_ = (c) >> 4; \
        int m0_ = (t_ >> 3) * 128, n0_ = (t_ & 7) * 128, k0_ = ((c) & 15) * 64; \
        const uint32_t sb_ = sb0 + (stg) * FSTG; \
        _Pragma("unroll") \
        for (int tt = 0; tt < 2; tt++) { \
            int idx = tid + tt*512; int r = idx >> 3, cc = idx & 7; \
            cp_async16(sb_ + FSAH + r*FPITCH + cc*16, A + (size_t)(m0_+r)*DM + k0_ + cc*8); \
            cp_async16(sb_ + FSBH + r*FPITCH + cc*16, B + (size_t)(n0_+r)*DM + k0_ + cc*8); \
        } \
        CP_COMMIT(); \
    } while (0)

    LOAD_CHUNK(s, 0);
    if (s + 1 < e) LOAD_CHUNK(s + 1, 1);
    int cur = 0;

    #pragma unroll 1
    for (int c = s; c < e; c++) {
        if (c + 1 < e) { CP_WAIT(1); } else { CP_WAIT(0); }
        __syncthreads();
        if (c + 2 < e) {
            int pf = cur - 1; if (pf < 0) pf = 2;
            LOAD_CHUNK(c + 2, pf);
        }

        const uint32_t sb = sb0 + cur * FSTG;
        cur = (cur == 2) ? 0 : cur + 1;

        // register double-buffered kk loop: prefetch kk+1 frags before kk MMAs
        uint32_t abuf[2][8], bbuf[2][8];
        LDSM4(abuf[0],     sb + abase);
        LDSM4(abuf[0] + 4, sb + abase + 16*FPITCH);
        LDSM4(bbuf[0],     sb + bbase);
        LDSM4(bbuf[0] + 4, sb + bbase + 16*FPITCH);
        #pragma unroll
        for (int kk = 0; kk < 4; kk++) {
            const int cb = kk & 1, nb = cb ^ 1;
            if (kk < 3) {
                const uint32_t koff = (kk + 1) * 32;
                LDSM4(abuf[nb],     sb + abase + koff);
                LDSM4(abuf[nb] + 4, sb + abase + 16*FPITCH + koff);
                LDSM4(bbuf[nb],     sb + bbase + koff);
                LDSM4(bbuf[nb] + 4, sb + bbase + 16*FPITCH + koff);
            }
            #pragma unroll
            for (int mt = 0; mt < 2; mt++)
                #pragma unroll
                for (int p = 0; p < 2; p++) {
                    MMAF16(acc + (mt*4 + 2*p)*4,   abuf[cb] + 4*mt, bbuf[cb][4*p+0], bbuf[cb][4*p+2]);
                    MMAF16(acc + (mt*4 + 2*p+1)*4, abuf[cb] + 4*mt, bbuf[cb][4*p+1], bbuf[cb][4*p+3]);
                }
        }

        const int t = c >> 4;
        if ((c & 15) == 15) {
            if (t * 16 >= s) {
                // full tile owned: write out
                const int rbase = (t >> 3) * 128 + wm*32 + (lane >> 2);
                const int cbase = (t & 7) * 128 + wn*32 + (lane & 3) * 2;
                #pragma unroll
                for (int mt = 0; mt < 2; mt++)
                    #pragma unroll
                    for (int nt = 0; nt < 4; nt++) {
                        const float* q = acc + (mt*4 + nt)*4;
                        int row = rbase + mt*16, col = cbase + nt*8;
                        if (OUT == 0) {
                            *(uint32_t*)&Ch[(size_t)row * ldc + col]     = pack_h2(q[0], q[1]);
                            *(uint32_t*)&Ch[(size_t)(row+8) * ldc + col] = pack_h2(q[2], q[3]);
                        } else {
                            float2 v0; v0.x = q[0]; v0.y = q[1];
                            float2 v1; v1.x = q[2]; v1.y = q[3];
                            *(float2*)&Cf[(size_t)row * ldc + col]       = v0;
                            *(float2*)&Cf[(size_t)(row + 8) * ldc + col] = v1;
                        }
                    }
            } else {
                // tail of split tile: post partial EARLY (first tile of range)
                float* slot = g_scr[cta] + (size_t)tid * FACC;
                #pragma unroll
                for (int i = 0; i < FACC; i += 4)
                    *(float4*)&slot[i] = *(float4*)&acc[i];
                __threadfence();
                __syncthreads();
                if (tid == 0) atomicExch(&g_flag[cta], 1);
            }
            #pragma unroll
            for (int i = 0; i < FACC; i++) acc[i] = 0.0f;
        } else if (c == e - 1) {
            // head of split tile: wait for cta+1's early post, add, write
            if (tid == 0) {
                while (atomicAdd(&g_flag[cta + 1], 0) == 0) { __nanosleep(64); }
                atomicExch(&g_flag[cta + 1], 0);
                __threadfence();
            }
            __syncthreads();
            const float* slot = g_scr[cta + 1] + (size_t)tid * FACC;
            #pragma unroll
            for (int i = 0; i < FACC; i += 4) {
                float4 v = __ldcv((const float4*)&slot[i]);
                acc[i+0] += v.x; acc[i+1] += v.y; acc[i+2] += v.z; acc[i+3] += v.w;
            }
            const int rbase = (t >> 3) * 128 + wm*32 + (lane >> 2);
            const int cbase = (t & 7) * 128 + wn*32 + (lane & 3) * 2;
            #pragma unroll
            for (int mt = 0; mt < 2; mt++)
                #pragma unroll
                for (int nt = 0; nt < 4; nt++) {
                    const float* q = acc + (mt*4 + nt)*4;
                    int row = rbase + mt*16, col = cbase + nt*8;
                    if (OUT == 0) {
                        *(uint32_t*)&Ch[(size_t)row * ldc + col]     = pack_h2(q[0], q[1]);
                        *(uint32_t*)&Ch[(size_t)(row+8) * ldc + col] = pack_h2(q[2], q[3]);
                    } else {
                        float2 v0; v0.x = q[0]; v0.y = q[1];
                        float2 v1; v1.x = q[2]; v1.y = q[3];
                        *(float2*)&Cf[(size_t)row * ldc + col]       = v0;
                        *(float2*)&Cf[(size_t)(row + 8) * ldc + col] = v1;
                    }
                }
        }
    }
    #undef LOAD_CHUNK
}

// ============== MMA flash attention (BQ=64, 4 warps, 3 CTAs/SM) =============
#define BQ 64
#define BK 64
#define PB 144
#define SQ_H 0
#define SQ_L 9216
#define STG0 18432
#define STGSZ 27648
#define ATTN_SMEM (STG0 + 2*STGSZ)   // 73728

__global__ __launch_bounds__(128, 3) void attn_mma() {
    extern __shared__ char smc[];
    const uint32_t sb = smem_u32(smc);
    const int tid  = threadIdx.x;
    const int w    = tid >> 5;
    const int lane = tid & 31;
    const int bh = blockIdx.y, h = bh & 15, b = bh >> 4;
    const int q0 = blockIdx.x * BQ;
    const int rowbase = b * SEQ;

    const unsigned short* gxh = g_xh;
    const unsigned short* gxl = g_xl;

    #pragma unroll
    for (int t = 0; t < 8; t++) {
        int idx = tid + t*128;
        int arr = idx >> 9;
        int i2  = idx & 511;
        int r   = i2 >> 3, cc = i2 & 7;
        const unsigned short* src = (arr ? gxl : gxh)
            + (size_t)(rowbase + q0 + r) * DM3 + h*DH + cc*8;
        cp_async16(sb + (arr ? SQ_L : SQ_H) + r*PB + cc*16, src);
    }

    #define LOADKV(j) do { \
        const uint32_t st_ = sb + STG0 + ((j) & 1) * STGSZ; \
        const int kk0 = (j) * BK; \
        _Pragma("unroll") \
        for (int t = 0; t < 12; t++) { \
            int idx = tid + t*128; \
            int arr = idx >> 9; int i2 = idx & 511; \
            int r = i2 >> 3, cc = i2 & 7; \
            const unsigned short* srcp = (arr == 0) ? (gxh + 1024) \
                                       : (arr == 1) ? (gxl + 1024) : (gxh + 2048); \
            srcp += (size_t)(rowbase + kk0 + r) * DM3 + h*DH + cc*8; \
            cp_async16(st_ + arr*9216 + r*PB + cc*16, srcp); \
        } \
    } while (0)

    LOADKV(0);
    CP_COMMIT();

    const uint32_t loff = (lane & 15) * PB + (lane >> 4) * 16;
    uint32_t qfh[4][4], qfl[4][4];

    float o[8][4];
    #pragma unroll
    for (int dt = 0; dt < 8; dt++)
        #pragma unroll
        for (int q = 0; q < 4; q++) o[dt][q] = 0.0f;
    float m0r = -1e30f, m1r = -1e30f, l0r = 0.0f, l1r = 0.0f;

    const float* bt = g_bias + h * 4096;
    const int row0 = lane >> 2;
    const int col2 = (lane & 3) * 2;

    #pragma unroll 1
    for (int i = 0; i < SEQ/BK; i++) {
        if (i + 1 < SEQ/BK) LOADKV(i + 1);
        CP_COMMIT();
        CP_WAIT(1);
        __syncthreads();

        if (i == 0) {
            #pragma unroll
            for (int ks = 0; ks < 4; ks++) {
                LDSM4(qfh[ks], sb + SQ_H + w*16*PB + loff + ks*32);
                LDSM4(qfl[ks], sb + SQ_L + w*16*PB + loff + ks*32);
            }
        }

        const uint32_t st = sb + STG0 + (i & 1) * STGSZ;

        float s[8][4];
        #pragma unroll
        for (int nt = 0; nt < 8; nt++)
            #pragma unroll
            for (int q = 0; q < 4; q++) s[nt][q] = 0.0f;

        #pragma unroll
        for (int ks = 0; ks < 4; ks++) {
            #pragma unroll
            for (int np = 0; np < 4; np++) {
                uint32_t bh4[4], bl4[4];
                LDSM4(bh4, st + (np*16)*PB + loff + ks*32);
                LDSM4(bl4, st + 9216 + (np*16)*PB + loff + ks*32);
                MMA16816(s[2*np],   qfh[ks], bh4[0], bh4[2]);
                MMA16816(s[2*np+1], qfh[ks], bh4[1], bh4[3]);
                MMA16816(s[2*np],   qfl[ks], bh4[0], bh4[2]);
                MMA16816(s[2*np+1], qfl[ks], bh4[1], bh4[3]);
                MMA16816(s[2*np],   qfh[ks], bl4[0], bl4[2]);
                MMA16816(s[2*np+1], qfh[ks], bl4[1], bl4[3]);
            }
        }

        const float* bp0 = bt + 2048 + i*BK + col2 - (q0 + w*16 + row0);
        #pragma unroll
        for (int nt = 0; nt < 8; nt++) {
            s[nt][0] += __ldg(bp0 + nt*8);
            s[nt][1] += __ldg(bp0 + nt*8 + 1);
            s[nt][2] += __ldg(bp0 + nt*8 - 8);
            s[nt][3] += __ldg(bp0 + nt*8 - 7);
        }

        float t0 = -1e30f, t1 = -1e30f;
        #pragma unroll
        for (int nt = 0; nt < 8; nt++) {
            t0 = fmaxf(t0, fmaxf(s[nt][0], s[nt][1]));
            t1 = fmaxf(t1, fmaxf(s[nt][2], s[nt][3]));
        }
        t0 = fmaxf(t0, __shfl_xor_sync(0xffffffffu, t0, 1));
        t0 = fmaxf(t0, __shfl_xor_sync(0xffffffffu, t0, 2));
        t1 = fmaxf(t1, __shfl_xor_sync(0xffffffffu, t1, 1));
        t1 = fmaxf(t1, __shfl_xor_sync(0xffffffffu, t1, 2));
        float mn0 = fmaxf(m0r, t0), mn1 = fmaxf(m1r, t1);
        float a0 = expp(m0r - mn0), a1 = expp(m1r - mn1);
        m0r = mn0; m1r = mn1;

        float ps0 = 0.0f, ps1 = 0.0f;
        #pragma unroll
        for (int nt = 0; nt < 8; nt++) {
            s[nt][0] = expp(s[nt][0] - mn0);
            s[nt][1] = expp(s[nt][1] - mn0);
            s[nt][2] = expp(s[nt][2] - mn1);
            s[nt][3] = expp(s[nt][3] - mn1);
            ps0 += s[nt][0] + s[nt][1];
            ps1 += s[nt][2] + s[nt][3];
        }
        ps0 += __shfl_xor_sync(0xffffffffu, ps0, 1);
        ps0 += __shfl_xor_sync(0xffffffffu, ps0, 2);
        ps1 += __shfl_xor_sync(0xffffffffu, ps1, 1);
        ps1 += __shfl_xor_sync(0xffffffffu, ps1, 2);
        l0r = l0r * a0 + ps0;
        l1r = l1r * a1 + ps1;
        #pragma unroll
        for (int dt = 0; dt < 8; dt++) {
            o[dt][0] *= a0; o[dt][1] *= a0;
            o[dt][2] *= a1; o[dt][3] *= a1;
        }

        #pragma unroll
        for (int ks = 0; ks < 4; ks++) {
            uint32_t ph4[4];
            #pragma unroll
            for (int q = 0; q < 4; q++) {
                int nt = 2*ks + (q >> 1);
                ph4[q] = pack_h2(s[nt][(q & 1) * 2], s[nt][(q & 1) * 2 + 1]);
            }
            #pragma unroll
            for (int dp = 0; dp < 4; dp++) {
                uint32_t vh4[4];
                LDSM4T(vh4, st + 18432 + (ks*16 + (lane & 15))*PB + dp*32 + (lane >> 4)*16);
                MMAF16(o[2*dp],   ph4, vh4[0], vh4[1]);
                MMAF16(o[2*dp+1], ph4, vh4[2], vh4[3]);
            }
        }
        __syncthreads();
    }
    #undef LOADKV

    float inv0 = 1.0f / l0r, inv1 = 1.0f / l1r;
    unsigned short* oh = g_ah;
    const size_t gr0 = (size_t)(rowbase + q0 + w*16 + row0) * DM + h*DH;
    const size_t gr1 = gr0 + 8 * DM;
    #pragma unroll
    for (int dt = 0; dt < 8; dt++) {
        int col = dt*8 + col2;
        *(uint32_t*)&oh[gr0 + col] = pack_h2(o[dt][0]*inv0, o[dt][1]*inv0);
        *(uint32_t*)&oh[gr1 + col] = pack_h2(o[dt][2]*inv1, o[dt][3]*inv1);
    }
}

// ---------------- launch -----------------------------------------------------
extern "C" void kernel_launch(void* const* d_in, const int* in_sizes, int n_in,
                              void* d_out, int out_size) {
    const float* hidden = (const float*)d_in[0];
    const float* Wq     = (const float*)d_in[1];
    const float* Wk     = (const float*)d_in[2];
    const float* Wv     = (const float*)d_in[3];
    const float* Wo     = (const float*)d_in[4];
    const float* relb   = (const float*)d_in[5];
    float* out = (float*)d_out;

    void *phh, *phl, *phf, *pxh, *pxl, *pah, *pwh, *pwl;
    cudaGetSymbolAddress(&phh, g_hh);
    cudaGetSymbolAddress(&phl, g_hl);
    cudaGetSymbolAddress(&phf, g_hf);
    cudaGetSymbolAddress(&pxh, g_xh);
    cudaGetSymbolAddress(&pxl, g_xl);
    cudaGetSymbolAddress(&pah, g_ah);
    cudaGetSymbolAddress(&pwh, g_wh);
    cudaGetSymbolAddress(&pwl, g_wl);

    unsigned short* hh = (unsigned short*)phh;
    unsigned short* hl = (unsigned short*)phl;
    unsigned short* hf = (unsigned short*)phf;
    unsigned short* xh = (unsigned short*)pxh;
    unsigned short* xl = (unsigned short*)pxl;
    unsigned short* ah = (unsigned short*)pah;
    unsigned short* wh = (unsigned short*)pwh;
    unsigned short* wl = (unsigned short*)pwl;

    int dev = 0, sms = GRID_SK;
    cudaGetDevice(&dev);
    cudaDeviceGetAttribute(&sms, cudaDevAttrMultiProcessorCount, dev);
    int grid1 = (sms < GRID_SK) ? sms : GRID_SK;

    convert_split<<<(MROWS*DM/4)/256, 256>>>(hidden, hh, hl, hf);
    convert_w_all<<<dim3(DM/32, DM/32, 5), dim3(32, 8)>>>(Wq, Wk, Wv, Wo, relb);

    const int QK_SMEM = 3 * QSTG;    // 184320
    const int F_SMEM  = 3 * FSTG;    // 110592
    cudaFuncSetAttribute(gemm_qk, cudaFuncAttributeMaxDynamicSharedMemorySize, QK_SMEM);
    cudaFuncSetAttribute(gemm_f512<0>, cudaFuncAttributeMaxDynamicSharedMemorySize, F_SMEM);
    cudaFuncSetAttribute(gemm_f512<1>, cudaFuncAttributeMaxDynamicSharedMemorySize, F_SMEM);

    // QK projections: N=2048, bf16 3-pass, out bf16 hi/lo into xh/xl cols 0..2047
    gemm_qk<<<grid1, 256, QK_SMEM>>>(hh, hl, wh, wl, xh, xl);

    // V projection: fp16 1-pass, 512 threads, K-chunk 64, out fp16 cols 2048..3071
    gemm_f512<0><<<grid1, 512, F_SMEM>>>(hf, wh + 2*(size_t)DM*DM,
                                         xh + 2048, nullptr, DM3);

    cudaFuncSetAttribute(attn_mma, cudaFuncAttributeMaxDynamicSharedMemorySize, ATTN_SMEM);
    attn_mma<<<dim3(SEQ/BQ, BATCH*NH), 128, ATTN_SMEM>>>();

    // Wo: fp16 1-pass, 512 threads, K-chunk 64, fp32 out
    gemm_f512<1><<<grid1, 512, F_SMEM>>>(ah, wh + 3*(size_t)DM*DM,
                                         nullptr, out, DM);
}